// round 14
// baseline (speedup 1.0000x reference)
#include <cuda_runtime.h>
#include <cuda_fp16.h>
#include <math.h>
#include <stdint.h>

#define NN    50000
#define EE    800000
#define INC   128
#define HIDC  64
#define NH    4
#define OUTC  64
#define F1    (NH * HIDC)        // 256
#define ET    (EE + NN)          // edges + self loops = 850000

// ---------------- scratch (device globals; no allocation) ----------------
__device__ __half g_h1h  [(size_t)NN * F1];   // x @ W1   (fp16 storage)
__device__ __half g_out1h[(size_t)NN * F1];   // z        (fp16 storage)
__device__ float  g_as1 [NN * NH];
__device__ float  g_ad1 [NN * NH];
__device__ __half g_h2h [(size_t)NN * OUTC];  // z @ W2   (fp16 storage)
__device__ __half g_out2h[(size_t)NN * OUTC]; // z2       (fp16 storage)
__device__ float  g_as2 [NN];
__device__ float  g_ad2 [NN];
// CSR by destination (shared by both conv layers)
__device__ int    g_off [NN + 1];
__device__ int    g_fill[NN];
__device__ int    g_srcidx[ET];

__device__ __forceinline__ float lrelu(float v) { return v > 0.f ? v : 0.2f * v; }

// ---------------- CSR build ----------------
__global__ void init_off_k() {
    int i = blockIdx.x * blockDim.x + threadIdx.x;
    if (i <= NN) g_off[i] = (i == 0) ? 0 : 1;   // each node has 1 self loop
}

__global__ void hist_k(const int* __restrict__ ei) {
    int e = blockIdx.x * blockDim.x + threadIdx.x;
    if (e >= EE) return;
    atomicAdd(&g_off[ei[EE + e] + 1], 1);
}

// single-block 3-phase inclusive scan over g_off[0..NN]
__global__ void scan_k() {
    const int L = NN + 1;
    const int CH = (L + 1023) / 1024;
    __shared__ int wsum[32];
    int t = threadIdx.x, lane = t & 31, wid = t >> 5;
    int beg = t * CH;
    int end = beg + CH; if (end > L) end = L;

    int s = 0;
    for (int i = beg; i < end; i++) s += g_off[i];

    int incl = s;
#pragma unroll
    for (int o = 1; o < 32; o <<= 1) {
        int v = __shfl_up_sync(0xffffffffu, incl, o);
        if (lane >= o) incl += v;
    }
    if (lane == 31) wsum[wid] = incl;
    __syncthreads();
    if (wid == 0) {
        int w = wsum[lane];
        int wi = w;
#pragma unroll
        for (int o = 1; o < 32; o <<= 1) {
            int v = __shfl_up_sync(0xffffffffu, wi, o);
            if (lane >= o) wi += v;
        }
        wsum[lane] = wi - w;
    }
    __syncthreads();

    int run = (incl - s) + wsum[wid];
    for (int i = beg; i < end; i++) {
        run += g_off[i];
        g_off[i] = run;
        if (i < NN) g_fill[i] = run;
    }
}

__global__ void scatter_k(const int* __restrict__ ei) {
    int e = blockIdx.x * blockDim.x + threadIdx.x;
    if (e >= ET) return;
    int s, d;
    if (e < EE) { s = ei[e]; d = ei[EE + e]; } else { s = d = e - EE; }
    int p = atomicAdd(&g_fill[d], 1);
    g_srcidx[p] = s;
}

// ---------------- fp16 tensor-core GEMM + fused attention --------------------
// C[M,N] = A[M,K] @ B[K,N]; BM=128, BN=64, BK=16; 8 warps, each 32x32.
#define AS_STRIDE 18

__device__ __forceinline__ void mma_f16(float* d, uint32_t a0, uint32_t a1,
                                        uint32_t a2, uint32_t a3,
                                        uint32_t b0, uint32_t b1) {
    asm volatile(
        "mma.sync.aligned.m16n8k16.row.col.f32.f16.f16.f32 "
        "{%0,%1,%2,%3}, {%4,%5,%6,%7}, {%8,%9}, {%0,%1,%2,%3};\n"
        : "+f"(d[0]), "+f"(d[1]), "+f"(d[2]), "+f"(d[3])
        : "r"(a0), "r"(a1), "r"(a2), "r"(a3), "r"(b0), "r"(b1));
}

// MODE 0: A = x (fp32 ext), C = g_h1h,  attn -> g_as1/g_ad1 per head (blockIdx.x)
// MODE 1: A = g_out1h (fp16), C = g_h2h, attn -> g_as2/g_ad2   [PDL secondary]
template <int MODE>
__global__ __launch_bounds__(256) void mma_gemm_k(const float* __restrict__ Aext,
                                                  const float* __restrict__ B,
                                                  const float* __restrict__ att_s,
                                                  const float* __restrict__ att_d,
                                                  int M, int N, int K) {
    __shared__ __align__(16) __half As[128 * AS_STRIDE];
    __shared__ __align__(16) __half Bs[64 * AS_STRIDE];
    __shared__ float sAs[128], sAd[128];

    int tid = threadIdx.x;
    int wid = tid >> 5, lane = tid & 31;
    int warp_m = wid >> 1, warp_n = wid & 1;
    int m_warp = warp_m * 32, n_warp = warp_n * 32;
    int g = lane >> 2, c = lane & 3;
    int rowBase = blockIdx.y * 128, colBase = blockIdx.x * 64;

    if (MODE == 1) cudaGridDependencySynchronize();   // wait for agg1's z

    if (tid < 128) { sAs[tid] = 0.f; sAd[tid] = 0.f; }

    float acc[2][4][4] = {};

    for (int k0 = 0; k0 < K; k0 += 16) {
        // ---- stage A: 128 rows x 16 k (halves) ----
        {
            int row = tid >> 1, kq = (tid & 1) * 8;
            int gm = rowBase + row;
            __half2 hv[4];
            if (MODE == 0) {
                float4 v0 = make_float4(0.f, 0.f, 0.f, 0.f), v1 = v0;
                if (gm < M) {
                    const float* ap = Aext + (size_t)gm * K + k0 + kq;
                    v0 = *(const float4*)ap;
                    v1 = *(const float4*)(ap + 4);
                }
                hv[0] = __floats2half2_rn(v0.x, v0.y);
                hv[1] = __floats2half2_rn(v0.z, v0.w);
                hv[2] = __floats2half2_rn(v1.x, v1.y);
                hv[3] = __floats2half2_rn(v1.z, v1.w);
            } else {
                if (gm < M) {
                    float4 p = *(const float4*)(g_out1h + (size_t)gm * K + k0 + kq);
                    const __half2* hp = (const __half2*)&p;
                    hv[0] = hp[0]; hv[1] = hp[1]; hv[2] = hp[2]; hv[3] = hp[3];
                } else {
                    hv[0] = hv[1] = hv[2] = hv[3] = __floats2half2_rn(0.f, 0.f);
                }
            }
            __half2* dst = (__half2*)&As[row * AS_STRIDE + kq];
            dst[0] = hv[0]; dst[1] = hv[1]; dst[2] = hv[2]; dst[3] = hv[3];
        }
        // ---- stage B transposed: Bs[n][k], 16 k x 64 n ----
        {
            int kr = tid >> 4, nq = (tid & 15) * 4;
            float4 v = *(const float4*)(B + (size_t)(k0 + kr) * N + colBase + nq);
            Bs[(nq + 0) * AS_STRIDE + kr] = __float2half_rn(v.x);
            Bs[(nq + 1) * AS_STRIDE + kr] = __float2half_rn(v.y);
            Bs[(nq + 2) * AS_STRIDE + kr] = __float2half_rn(v.z);
            Bs[(nq + 3) * AS_STRIDE + kr] = __float2half_rn(v.w);
        }
        __syncthreads();

        uint32_t a[2][4], b[4][2];
#pragma unroll
        for (int t = 0; t < 2; t++) {
            int r0 = (m_warp + t * 16 + g) * AS_STRIDE + 2 * c;
            int r1 = r0 + 8 * AS_STRIDE;
            a[t][0] = *(const uint32_t*)&As[r0];
            a[t][1] = *(const uint32_t*)&As[r1];
            a[t][2] = *(const uint32_t*)&As[r0 + 8];
            a[t][3] = *(const uint32_t*)&As[r1 + 8];
        }
#pragma unroll
        for (int j = 0; j < 4; j++) {
            int nb = (n_warp + j * 8 + g) * AS_STRIDE + 2 * c;
            b[j][0] = *(const uint32_t*)&Bs[nb];
            b[j][1] = *(const uint32_t*)&Bs[nb + 8];
        }
#pragma unroll
        for (int t = 0; t < 2; t++)
#pragma unroll
            for (int j = 0; j < 4; j++)
                mma_f16(acc[t][j], a[t][0], a[t][1], a[t][2], a[t][3], b[j][0], b[j][1]);
        __syncthreads();
    }

    // write C as fp16
    __half* Ch = (MODE == 0) ? g_h1h : g_h2h;
#pragma unroll
    for (int t = 0; t < 2; t++)
#pragma unroll
        for (int j = 0; j < 4; j++) {
            int r0 = rowBase + m_warp + t * 16 + g;
            int r1 = r0 + 8;
            int cc = colBase + n_warp + j * 8 + 2 * c;
            if (r0 < M)
                *(__half2*)&Ch[(size_t)r0 * N + cc] = __floats2half2_rn(acc[t][j][0], acc[t][j][1]);
            if (r1 < M)
                *(__half2*)&Ch[(size_t)r1 * N + cc] = __floats2half2_rn(acc[t][j][2], acc[t][j][3]);
        }

    // fused attention dots over this block's 64 columns
#pragma unroll
    for (int t = 0; t < 2; t++) {
        float s0 = 0.f, d0 = 0.f, s1 = 0.f, d1 = 0.f;
#pragma unroll
        for (int j = 0; j < 4; j++) {
            int cg = colBase + n_warp + j * 8 + 2 * c;
            float w0 = __ldg(att_s + cg), w1 = __ldg(att_s + cg + 1);
            float v0 = __ldg(att_d + cg), v1 = __ldg(att_d + cg + 1);
            s0 += acc[t][j][0] * w0 + acc[t][j][1] * w1;
            d0 += acc[t][j][0] * v0 + acc[t][j][1] * v1;
            s1 += acc[t][j][2] * w0 + acc[t][j][3] * w1;
            d1 += acc[t][j][2] * v0 + acc[t][j][3] * v1;
        }
#pragma unroll
        for (int o = 1; o < 4; o <<= 1) {
            s0 += __shfl_xor_sync(0xffffffffu, s0, o);
            d0 += __shfl_xor_sync(0xffffffffu, d0, o);
            s1 += __shfl_xor_sync(0xffffffffu, s1, o);
            d1 += __shfl_xor_sync(0xffffffffu, d1, o);
        }
        if (c == 0) {
            int rl = m_warp + t * 16 + g;
            atomicAdd(&sAs[rl], s0);     atomicAdd(&sAd[rl], d0);
            atomicAdd(&sAs[rl + 8], s1); atomicAdd(&sAd[rl + 8], d1);
        }
    }
    __syncthreads();
    if (tid < 128) {
        int gm = rowBase + tid;
        if (gm < M) {
            if (MODE == 0) {
                g_as1[gm * NH + blockIdx.x] = sAs[tid];
                g_ad1[gm * NH + blockIdx.x] = sAd[tid];
            } else {
                g_as2[gm] = sAs[tid];
                g_ad2[gm] = sAd[tid];
            }
        }
    }
}

// ---------------- conv1: single-pass aggregation (deferred softmax division) -
// warp per node; lane owns 8 columns (lane*8..+7), head = lane>>3.
// out = (Σ_k e_k * h_jk) / (Σ_k e_k)  — division deferred to the end.
__global__ __launch_bounds__(256) void agg1_k(const float* __restrict__ b1) {
    int gtid = blockIdx.x * blockDim.x + threadIdx.x;
    int node = gtid >> 5, lane = gtid & 31;
    if (node >= NN) return;
    int beg = g_off[node], end = g_off[node + 1];

    cudaGridDependencySynchronize();                  // wait for gemm1 outputs

    float4 ad = *(const float4*)(g_ad1 + node * 4);
    const bool s8 = (lane & 8) != 0, s16 = (lane & 16) != 0;
    const int col = lane * 8;

    float av[8] = {};
    float den = 0.f;

    int k = beg;
    for (; k + 2 <= end; k += 2) {
        int j0 = g_srcidx[k], j1 = g_srcidx[k + 1];        // broadcast
        float4 a0 = *(const float4*)(g_as1 + j0 * 4);      // broadcast
        float4 a1 = *(const float4*)(g_as1 + j1 * 4);
        float4 p0 = *(const float4*)(g_h1h + (size_t)j0 * F1 + col);  // 512B/warp
        float4 p1 = *(const float4*)(g_h1h + (size_t)j1 * F1 + col);
        float e00 = __expf(lrelu(a0.x + ad.x)), e01 = __expf(lrelu(a0.y + ad.y));
        float e02 = __expf(lrelu(a0.z + ad.z)), e03 = __expf(lrelu(a0.w + ad.w));
        float e10 = __expf(lrelu(a1.x + ad.x)), e11 = __expf(lrelu(a1.y + ad.y));
        float e12 = __expf(lrelu(a1.z + ad.z)), e13 = __expf(lrelu(a1.w + ad.w));
        float w0 = s16 ? (s8 ? e03 : e02) : (s8 ? e01 : e00);
        float w1 = s16 ? (s8 ? e13 : e12) : (s8 ? e11 : e10);
        den += w0 + w1;
        const __half2* h0 = (const __half2*)&p0;
        const __half2* h1 = (const __half2*)&p1;
#pragma unroll
        for (int i = 0; i < 4; i++) {
            float2 f0 = __half22float2(h0[i]);
            float2 f1 = __half22float2(h1[i]);
            av[2 * i + 0] += w0 * f0.x + w1 * f1.x;
            av[2 * i + 1] += w0 * f0.y + w1 * f1.y;
        }
    }
    if (k < end) {
        int j0 = g_srcidx[k];
        float4 a0 = *(const float4*)(g_as1 + j0 * 4);
        float4 p0 = *(const float4*)(g_h1h + (size_t)j0 * F1 + col);
        float e00 = __expf(lrelu(a0.x + ad.x)), e01 = __expf(lrelu(a0.y + ad.y));
        float e02 = __expf(lrelu(a0.z + ad.z)), e03 = __expf(lrelu(a0.w + ad.w));
        float w0 = s16 ? (s8 ? e03 : e02) : (s8 ? e01 : e00);
        den += w0;
        const __half2* h0 = (const __half2*)&p0;
#pragma unroll
        for (int i = 0; i < 4; i++) {
            float2 f0 = __half22float2(h0[i]);
            av[2 * i + 0] += w0 * f0.x;
            av[2 * i + 1] += w0 * f0.y;
        }
    }

    float inv = 1.f / (den + 1e-16f);
    float4 bA = *(const float4*)(b1 + col);
    float4 bB = *(const float4*)(b1 + col + 4);
    __half2 pack[4];
    pack[0] = __floats2half2_rn(fmaxf(av[0] * inv + bA.x, 0.f), fmaxf(av[1] * inv + bA.y, 0.f));
    pack[1] = __floats2half2_rn(fmaxf(av[2] * inv + bA.z, 0.f), fmaxf(av[3] * inv + bA.w, 0.f));
    pack[2] = __floats2half2_rn(fmaxf(av[4] * inv + bB.x, 0.f), fmaxf(av[5] * inv + bB.y, 0.f));
    pack[3] = __floats2half2_rn(fmaxf(av[6] * inv + bB.z, 0.f), fmaxf(av[7] * inv + bB.w, 0.f));
    *(float4*)(g_out1h + (size_t)node * F1 + col) = *(const float4*)pack;
}

// ---------------- conv2: single-pass aggregation (deferred division) ---------
__global__ __launch_bounds__(256) void agg2_k(const float* __restrict__ b2) {
    int gtid = blockIdx.x * blockDim.x + threadIdx.x;
    int node = gtid >> 5, lane = gtid & 31;
    if (node >= NN) return;
    int beg = g_off[node], end = g_off[node + 1];

    cudaGridDependencySynchronize();                  // wait for gemm2 outputs

    float ad = g_ad2[node];
    const int c = lane * 2;
    float a0 = 0.f, a1 = 0.f, den = 0.f;

    int k = beg;
    for (; k + 2 <= end; k += 2) {
        int j0 = g_srcidx[k], j1 = g_srcidx[k + 1];
        float e0 = __expf(lrelu(g_as2[j0] + ad));
        float e1 = __expf(lrelu(g_as2[j1] + ad));
        float2 v0 = __half22float2(*(const __half2*)(g_h2h + (size_t)j0 * OUTC + c));
        float2 v1 = __half22float2(*(const __half2*)(g_h2h + (size_t)j1 * OUTC + c));
        den += e0 + e1;
        a0 += e0 * v0.x + e1 * v1.x;
        a1 += e0 * v0.y + e1 * v1.y;
    }
    if (k < end) {
        int j0 = g_srcidx[k];
        float e0 = __expf(lrelu(g_as2[j0] + ad));
        float2 v0 = __half22float2(*(const __half2*)(g_h2h + (size_t)j0 * OUTC + c));
        den += e0;
        a0 += e0 * v0.x; a1 += e0 * v0.y;
    }

    float inv = 1.f / (den + 1e-16f);
    float2 bb = *(const float2*)(b2 + c);
    *(__half2*)(g_out2h + (size_t)node * OUTC + c) =
        __floats2half2_rn(a0 * inv + bb.x, a1 * inv + bb.y);
}

// ---------------- decode: logits (8 lanes per edge, 4 edges per warp) --------
__global__ __launch_bounds__(256) void decode_k(const int* __restrict__ pos,
                                                const int* __restrict__ neg,
                                                float* __restrict__ out) {
    int g = blockIdx.x * blockDim.x + threadIdx.x;
    int e = g >> 3, lane = g & 7;
    if (e >= 2 * EE) return;
    int a, b;
    if (e < EE) { a = pos[e]; b = pos[EE + e]; }
    else        { int t = e - EE; a = neg[t]; b = neg[EE + t]; }

    cudaGridDependencySynchronize();      // index loads above overlap agg2 tail

    int c = lane * 8;
    float4 pa = *(const float4*)(g_out2h + (size_t)a * OUTC + c);
    float4 pb = *(const float4*)(g_out2h + (size_t)b * OUTC + c);
    const __half2* ha = (const __half2*)&pa;
    const __half2* hb = (const __half2*)&pb;
    float acc = 0.f;
#pragma unroll
    for (int i = 0; i < 4; i++) {
        float2 fa = __half22float2(ha[i]);
        float2 fb = __half22float2(hb[i]);
        acc += fa.x * fb.x + fa.y * fb.y;
    }
#pragma unroll
    for (int o = 4; o; o >>= 1) acc += __shfl_xor_sync(0xffffffffu, acc, o);
    if (!lane) out[e] = acc;
}

// ---------------- launch ----------------
extern "C" void kernel_launch(void* const* d_in, const int* in_sizes, int n_in,
                              void* d_out, int out_size) {
    const float* x    = (const float*)d_in[0];
    const int*   pos  = (const int*)d_in[1];
    const int*   neg  = (const int*)d_in[2];
    const float* W1   = (const float*)d_in[3];
    const float* as1v = (const float*)d_in[4];
    const float* ad1v = (const float*)d_in[5];
    const float* b1   = (const float*)d_in[6];
    const float* W2   = (const float*)d_in[7];
    const float* as2v = (const float*)d_in[8];
    const float* ad2v = (const float*)d_in[9];
    const float* b2   = (const float*)d_in[10];
    float* out = (float*)d_out;
    (void)in_sizes; (void)n_in; (void)out_size;

    static cudaStream_t s1 = nullptr;
    static cudaEvent_t evFork = nullptr, evJoin = nullptr;
    if (s1 == nullptr) {
        cudaStreamCreateWithFlags(&s1, cudaStreamNonBlocking);
        cudaEventCreateWithFlags(&evFork, cudaEventDisableTiming);
        cudaEventCreateWithFlags(&evJoin, cudaEventDisableTiming);
    }

    // PDL launch config (opportunistic overlap with preceding kernel)
    cudaLaunchAttribute pdlAttr[1];
    pdlAttr[0].id = cudaLaunchAttributeProgrammaticStreamSerialization;
    pdlAttr[0].val.programmaticStreamSerializationAllowed = 1;

    // fork: CSR build on s1, concurrent with gemm1 on the main stream
    cudaEventRecord(evFork, 0);
    cudaStreamWaitEvent(s1, evFork, 0);
    init_off_k<<<(NN + 256) / 256, 256, 0, s1>>>();
    hist_k<<<(EE + 255) / 256, 256, 0, s1>>>(pos);
    scan_k<<<1, 1024, 0, s1>>>();
    scatter_k<<<(ET + 255) / 256, 256, 0, s1>>>(pos);
    cudaEventRecord(evJoin, s1);

    // conv1 linear + fused attention dots (normal launch)
    mma_gemm_k<0><<<dim3(F1 / 64, (NN + 127) / 128), 256>>>(x, W1, as1v, ad1v, NN, F1, INC);

    cudaStreamWaitEvent(0, evJoin, 0);

    // agg1 (PDL secondary of gemm1)
    {
        cudaLaunchConfig_t cfg = {};
        cfg.gridDim = dim3((NN * 32 + 255) / 256); cfg.blockDim = dim3(256);
        cfg.stream = 0; cfg.attrs = pdlAttr; cfg.numAttrs = 1;
        cudaLaunchKernelEx(&cfg, agg1_k, b1);
    }
    // gemm2 (PDL secondary of agg1)
    {
        cudaLaunchConfig_t cfg = {};
        cfg.gridDim = dim3(OUTC / 64, (NN + 127) / 128); cfg.blockDim = dim3(256);
        cfg.stream = 0; cfg.attrs = pdlAttr; cfg.numAttrs = 1;
        cudaLaunchKernelEx(&cfg, mma_gemm_k<1>, (const float*)nullptr, W2, as2v, ad2v,
                           (int)NN, (int)OUTC, (int)F1);
    }
    // agg2 (PDL secondary of gemm2)
    {
        cudaLaunchConfig_t cfg = {};
        cfg.gridDim = dim3((NN * 32 + 255) / 256); cfg.blockDim = dim3(256);
        cfg.stream = 0; cfg.attrs = pdlAttr; cfg.numAttrs = 1;
        cudaLaunchKernelEx(&cfg, agg2_k, b2);
    }
    // decode (PDL secondary of agg2)
    {
        cudaLaunchConfig_t cfg = {};
        cfg.gridDim = dim3((2 * EE * 8 + 255) / 256); cfg.blockDim = dim3(256);
        cfg.stream = 0; cfg.attrs = pdlAttr; cfg.numAttrs = 1;
        cudaLaunchKernelEx(&cfg, decode_k, pos, neg, out);
    }
}

// round 15
// speedup vs baseline: 1.0602x; 1.0602x over previous
#include <cuda_runtime.h>
#include <cuda_fp16.h>
#include <math.h>
#include <stdint.h>

#define NN    50000
#define EE    800000
#define INC   128
#define HIDC  64
#define NH    4
#define OUTC  64
#define F1    (NH * HIDC)        // 256
#define ET    (EE + NN)          // edges + self loops = 850000

// ---------------- scratch (device globals; no allocation) ----------------
__device__ __half g_h1h  [(size_t)NN * F1];   // x @ W1   (fp16 storage)
__device__ __half g_out1h[(size_t)NN * F1];   // z        (fp16 storage)
__device__ float  g_as1 [NN * NH];
__device__ float  g_ad1 [NN * NH];
__device__ __half g_h2h [(size_t)NN * OUTC];  // z @ W2   (fp16 storage)
__device__ __half g_out2h[(size_t)NN * OUTC]; // z2       (fp16 storage)
__device__ float  g_as2 [NN];
__device__ float  g_ad2 [NN];
// CSR by destination (shared by both conv layers)
__device__ int    g_off [NN + 1];
__device__ int    g_fill[NN];
__device__ int    g_srcidx[ET];

__device__ __forceinline__ float lrelu(float v) { return v > 0.f ? v : 0.2f * v; }

// ---------------- CSR build ----------------
__global__ void init_off_k() {
    int i = blockIdx.x * blockDim.x + threadIdx.x;
    if (i <= NN) g_off[i] = (i == 0) ? 0 : 1;   // each node has 1 self loop
}

__global__ void hist_k(const int* __restrict__ ei) {
    int e = blockIdx.x * blockDim.x + threadIdx.x;
    if (e >= EE) return;
    atomicAdd(&g_off[ei[EE + e] + 1], 1);
}

// single-block 3-phase inclusive scan over g_off[0..NN]
__global__ void scan_k() {
    const int L = NN + 1;
    const int CH = (L + 1023) / 1024;
    __shared__ int wsum[32];
    int t = threadIdx.x, lane = t & 31, wid = t >> 5;
    int beg = t * CH;
    int end = beg + CH; if (end > L) end = L;

    int s = 0;
    for (int i = beg; i < end; i++) s += g_off[i];

    int incl = s;
#pragma unroll
    for (int o = 1; o < 32; o <<= 1) {
        int v = __shfl_up_sync(0xffffffffu, incl, o);
        if (lane >= o) incl += v;
    }
    if (lane == 31) wsum[wid] = incl;
    __syncthreads();
    if (wid == 0) {
        int w = wsum[lane];
        int wi = w;
#pragma unroll
        for (int o = 1; o < 32; o <<= 1) {
            int v = __shfl_up_sync(0xffffffffu, wi, o);
            if (lane >= o) wi += v;
        }
        wsum[lane] = wi - w;
    }
    __syncthreads();

    int run = (incl - s) + wsum[wid];
    for (int i = beg; i < end; i++) {
        run += g_off[i];
        g_off[i] = run;
        if (i < NN) g_fill[i] = run;
    }
}

__global__ void scatter_k(const int* __restrict__ ei) {
    int e = blockIdx.x * blockDim.x + threadIdx.x;
    if (e >= ET) return;
    int s, d;
    if (e < EE) { s = ei[e]; d = ei[EE + e]; } else { s = d = e - EE; }
    int p = atomicAdd(&g_fill[d], 1);
    g_srcidx[p] = s;
}

// ---------------- fp16 tensor-core GEMM + fused attention --------------------
// C[M,N] = A[M,K] @ B[K,N]; BM=128, BN=64, BK=16; 8 warps, each 32x32.
#define AS_STRIDE 18

__device__ __forceinline__ void mma_f16(float* d, uint32_t a0, uint32_t a1,
                                        uint32_t a2, uint32_t a3,
                                        uint32_t b0, uint32_t b1) {
    asm volatile(
        "mma.sync.aligned.m16n8k16.row.col.f32.f16.f16.f32 "
        "{%0,%1,%2,%3}, {%4,%5,%6,%7}, {%8,%9}, {%0,%1,%2,%3};\n"
        : "+f"(d[0]), "+f"(d[1]), "+f"(d[2]), "+f"(d[3])
        : "r"(a0), "r"(a1), "r"(a2), "r"(a3), "r"(b0), "r"(b1));
}

// MODE 0: A = x (fp32 ext), C = g_h1h,  attn -> g_as1/g_ad1 per head (blockIdx.x)
// MODE 1: A = g_out1h (fp16), C = g_h2h, attn -> g_as2/g_ad2   [PDL secondary]
template <int MODE>
__global__ __launch_bounds__(256) void mma_gemm_k(const float* __restrict__ Aext,
                                                  const float* __restrict__ B,
                                                  const float* __restrict__ att_s,
                                                  const float* __restrict__ att_d,
                                                  int M, int N, int K) {
    __shared__ __align__(16) __half As[128 * AS_STRIDE];
    __shared__ __align__(16) __half Bs[64 * AS_STRIDE];
    __shared__ float sAs[128], sAd[128];

    int tid = threadIdx.x;
    int wid = tid >> 5, lane = tid & 31;
    int warp_m = wid >> 1, warp_n = wid & 1;
    int m_warp = warp_m * 32, n_warp = warp_n * 32;
    int g = lane >> 2, c = lane & 3;
    int rowBase = blockIdx.y * 128, colBase = blockIdx.x * 64;

    if (MODE == 1) cudaGridDependencySynchronize();   // wait for agg1's z

    if (tid < 128) { sAs[tid] = 0.f; sAd[tid] = 0.f; }

    float acc[2][4][4] = {};

    for (int k0 = 0; k0 < K; k0 += 16) {
        // ---- stage A: 128 rows x 16 k (halves) ----
        {
            int row = tid >> 1, kq = (tid & 1) * 8;
            int gm = rowBase + row;
            __half2 hv[4];
            if (MODE == 0) {
                float4 v0 = make_float4(0.f, 0.f, 0.f, 0.f), v1 = v0;
                if (gm < M) {
                    const float* ap = Aext + (size_t)gm * K + k0 + kq;
                    v0 = *(const float4*)ap;
                    v1 = *(const float4*)(ap + 4);
                }
                hv[0] = __floats2half2_rn(v0.x, v0.y);
                hv[1] = __floats2half2_rn(v0.z, v0.w);
                hv[2] = __floats2half2_rn(v1.x, v1.y);
                hv[3] = __floats2half2_rn(v1.z, v1.w);
            } else {
                if (gm < M) {
                    float4 p = *(const float4*)(g_out1h + (size_t)gm * K + k0 + kq);
                    const __half2* hp = (const __half2*)&p;
                    hv[0] = hp[0]; hv[1] = hp[1]; hv[2] = hp[2]; hv[3] = hp[3];
                } else {
                    hv[0] = hv[1] = hv[2] = hv[3] = __floats2half2_rn(0.f, 0.f);
                }
            }
            __half2* dst = (__half2*)&As[row * AS_STRIDE + kq];
            dst[0] = hv[0]; dst[1] = hv[1]; dst[2] = hv[2]; dst[3] = hv[3];
        }
        // ---- stage B transposed: Bs[n][k], 16 k x 64 n ----
        {
            int kr = tid >> 4, nq = (tid & 15) * 4;
            float4 v = *(const float4*)(B + (size_t)(k0 + kr) * N + colBase + nq);
            Bs[(nq + 0) * AS_STRIDE + kr] = __float2half_rn(v.x);
            Bs[(nq + 1) * AS_STRIDE + kr] = __float2half_rn(v.y);
            Bs[(nq + 2) * AS_STRIDE + kr] = __float2half_rn(v.z);
            Bs[(nq + 3) * AS_STRIDE + kr] = __float2half_rn(v.w);
        }
        __syncthreads();

        uint32_t a[2][4], b[4][2];
#pragma unroll
        for (int t = 0; t < 2; t++) {
            int r0 = (m_warp + t * 16 + g) * AS_STRIDE + 2 * c;
            int r1 = r0 + 8 * AS_STRIDE;
            a[t][0] = *(const uint32_t*)&As[r0];
            a[t][1] = *(const uint32_t*)&As[r1];
            a[t][2] = *(const uint32_t*)&As[r0 + 8];
            a[t][3] = *(const uint32_t*)&As[r1 + 8];
        }
#pragma unroll
        for (int j = 0; j < 4; j++) {
            int nb = (n_warp + j * 8 + g) * AS_STRIDE + 2 * c;
            b[j][0] = *(const uint32_t*)&Bs[nb];
            b[j][1] = *(const uint32_t*)&Bs[nb + 8];
        }
#pragma unroll
        for (int t = 0; t < 2; t++)
#pragma unroll
            for (int j = 0; j < 4; j++)
                mma_f16(acc[t][j], a[t][0], a[t][1], a[t][2], a[t][3], b[j][0], b[j][1]);
        __syncthreads();
    }

    // write C as fp16
    __half* Ch = (MODE == 0) ? g_h1h : g_h2h;
#pragma unroll
    for (int t = 0; t < 2; t++)
#pragma unroll
        for (int j = 0; j < 4; j++) {
            int r0 = rowBase + m_warp + t * 16 + g;
            int r1 = r0 + 8;
            int cc = colBase + n_warp + j * 8 + 2 * c;
            if (r0 < M)
                *(__half2*)&Ch[(size_t)r0 * N + cc] = __floats2half2_rn(acc[t][j][0], acc[t][j][1]);
            if (r1 < M)
                *(__half2*)&Ch[(size_t)r1 * N + cc] = __floats2half2_rn(acc[t][j][2], acc[t][j][3]);
        }

    // fused attention dots over this block's 64 columns
#pragma unroll
    for (int t = 0; t < 2; t++) {
        float s0 = 0.f, d0 = 0.f, s1 = 0.f, d1 = 0.f;
#pragma unroll
        for (int j = 0; j < 4; j++) {
            int cg = colBase + n_warp + j * 8 + 2 * c;
            float w0 = __ldg(att_s + cg), w1 = __ldg(att_s + cg + 1);
            float v0 = __ldg(att_d + cg), v1 = __ldg(att_d + cg + 1);
            s0 += acc[t][j][0] * w0 + acc[t][j][1] * w1;
            d0 += acc[t][j][0] * v0 + acc[t][j][1] * v1;
            s1 += acc[t][j][2] * w0 + acc[t][j][3] * w1;
            d1 += acc[t][j][2] * v0 + acc[t][j][3] * v1;
        }
#pragma unroll
        for (int o = 1; o < 4; o <<= 1) {
            s0 += __shfl_xor_sync(0xffffffffu, s0, o);
            d0 += __shfl_xor_sync(0xffffffffu, d0, o);
            s1 += __shfl_xor_sync(0xffffffffu, s1, o);
            d1 += __shfl_xor_sync(0xffffffffu, d1, o);
        }
        if (c == 0) {
            int rl = m_warp + t * 16 + g;
            atomicAdd(&sAs[rl], s0);     atomicAdd(&sAd[rl], d0);
            atomicAdd(&sAs[rl + 8], s1); atomicAdd(&sAd[rl + 8], d1);
        }
    }
    __syncthreads();
    if (tid < 128) {
        int gm = rowBase + tid;
        if (gm < M) {
            if (MODE == 0) {
                g_as1[gm * NH + blockIdx.x] = sAs[tid];
                g_ad1[gm * NH + blockIdx.x] = sAd[tid];
            } else {
                g_as2[gm] = sAs[tid];
                g_ad2[gm] = sAd[tid];
            }
        }
    }
}

// ---------------- conv1: fused softmax+aggregation (warp/node, smem-staged) --
#define CAP 64
__global__ __launch_bounds__(256) void agg1_k(const float* __restrict__ b1) {
    __shared__ int    sj[8][CAP];
    __shared__ float4 se[8][CAP];
    int wslot = threadIdx.x >> 5, lane = threadIdx.x & 31;
    int node = blockIdx.x * 8 + wslot;
    if (node >= NN) return;
    int beg = g_off[node], deg = g_off[node + 1] - beg;   // CSR: event-ordered, safe

    cudaGridDependencySynchronize();                       // wait for gemm1 outputs

    float4 ad = *(const float4*)(g_ad1 + node * 4);
    float d0 = 0.f, d1 = 0.f, d2 = 0.f, d3 = 0.f;
    for (int kk = lane; kk < deg; kk += 32) {
        int j = g_srcidx[beg + kk];
        float4 as = *(const float4*)(g_as1 + j * 4);
        float e0 = __expf(lrelu(as.x + ad.x));
        float e1 = __expf(lrelu(as.y + ad.y));
        float e2 = __expf(lrelu(as.z + ad.z));
        float e3 = __expf(lrelu(as.w + ad.w));
        d0 += e0; d1 += e1; d2 += e2; d3 += e3;
        if (kk < CAP) { sj[wslot][kk] = j; se[wslot][kk] = make_float4(e0, e1, e2, e3); }
    }
#pragma unroll
    for (int o = 16; o; o >>= 1) {
        d0 += __shfl_xor_sync(0xffffffffu, d0, o);
        d1 += __shfl_xor_sync(0xffffffffu, d1, o);
        d2 += __shfl_xor_sync(0xffffffffu, d2, o);
        d3 += __shfl_xor_sync(0xffffffffu, d3, o);
    }
    float i0 = 1.f / (d0 + 1e-16f), i1 = 1.f / (d1 + 1e-16f);
    float i2 = 1.f / (d2 + 1e-16f), i3 = 1.f / (d3 + 1e-16f);
    __syncwarp();

    const bool s8 = (lane & 8) != 0, s16 = (lane & 16) != 0;
    float av[8] = {};
    int col = lane * 8;
    int cap = deg < CAP ? deg : CAP;

    int kk = 0;
    for (; kk + 4 <= cap; kk += 4) {
        int j0 = sj[wslot][kk],     j1 = sj[wslot][kk + 1];
        int j2 = sj[wslot][kk + 2], j3 = sj[wslot][kk + 3];
        float4 e0v = se[wslot][kk],     e1v = se[wslot][kk + 1];
        float4 e2v = se[wslot][kk + 2], e3v = se[wslot][kk + 3];
        float w0 = s16 ? (s8 ? e0v.w * i3 : e0v.z * i2) : (s8 ? e0v.y * i1 : e0v.x * i0);
        float w1 = s16 ? (s8 ? e1v.w * i3 : e1v.z * i2) : (s8 ? e1v.y * i1 : e1v.x * i0);
        float w2 = s16 ? (s8 ? e2v.w * i3 : e2v.z * i2) : (s8 ? e2v.y * i1 : e2v.x * i0);
        float w3 = s16 ? (s8 ? e3v.w * i3 : e3v.z * i2) : (s8 ? e3v.y * i1 : e3v.x * i0);
        float4 p0 = *(const float4*)(g_h1h + (size_t)j0 * F1 + col);
        float4 p1 = *(const float4*)(g_h1h + (size_t)j1 * F1 + col);
        float4 p2 = *(const float4*)(g_h1h + (size_t)j2 * F1 + col);
        float4 p3 = *(const float4*)(g_h1h + (size_t)j3 * F1 + col);
        const __half2* h0 = (const __half2*)&p0;
        const __half2* h1 = (const __half2*)&p1;
        const __half2* h2 = (const __half2*)&p2;
        const __half2* h3 = (const __half2*)&p3;
#pragma unroll
        for (int i = 0; i < 4; i++) {
            float2 f0 = __half22float2(h0[i]);
            float2 f1 = __half22float2(h1[i]);
            float2 f2 = __half22float2(h2[i]);
            float2 f3 = __half22float2(h3[i]);
            av[2 * i + 0] += w0 * f0.x + w1 * f1.x + w2 * f2.x + w3 * f3.x;
            av[2 * i + 1] += w0 * f0.y + w1 * f1.y + w2 * f2.y + w3 * f3.y;
        }
    }
    for (; kk < cap; kk++) {
        int j0 = sj[wslot][kk];
        float4 e0v = se[wslot][kk];
        float w0 = s16 ? (s8 ? e0v.w * i3 : e0v.z * i2) : (s8 ? e0v.y * i1 : e0v.x * i0);
        float4 p0 = *(const float4*)(g_h1h + (size_t)j0 * F1 + col);
        const __half2* h0 = (const __half2*)&p0;
#pragma unroll
        for (int i = 0; i < 4; i++) {
            float2 f0 = __half22float2(h0[i]);
            av[2 * i + 0] += w0 * f0.x;
            av[2 * i + 1] += w0 * f0.y;
        }
    }
    for (; kk < deg; kk++) {      // rare fallback: degree > CAP
        int j0 = g_srcidx[beg + kk];
        float4 as = *(const float4*)(g_as1 + j0 * 4);
        float e0 = __expf(lrelu(as.x + ad.x));
        float e1 = __expf(lrelu(as.y + ad.y));
        float e2 = __expf(lrelu(as.z + ad.z));
        float e3 = __expf(lrelu(as.w + ad.w));
        float w0 = s16 ? (s8 ? e3 * i3 : e2 * i2) : (s8 ? e1 * i1 : e0 * i0);
        float4 p0 = *(const float4*)(g_h1h + (size_t)j0 * F1 + col);
        const __half2* h0 = (const __half2*)&p0;
#pragma unroll
        for (int i = 0; i < 4; i++) {
            float2 f0 = __half22float2(h0[i]);
            av[2 * i + 0] += w0 * f0.x;
            av[2 * i + 1] += w0 * f0.y;
        }
    }

    float4 bA = *(const float4*)(b1 + col);
    float4 bB = *(const float4*)(b1 + col + 4);
    __half2 pack[4];
    pack[0] = __floats2half2_rn(fmaxf(av[0] + bA.x, 0.f), fmaxf(av[1] + bA.y, 0.f));
    pack[1] = __floats2half2_rn(fmaxf(av[2] + bA.z, 0.f), fmaxf(av[3] + bA.w, 0.f));
    pack[2] = __floats2half2_rn(fmaxf(av[4] + bB.x, 0.f), fmaxf(av[5] + bB.y, 0.f));
    pack[3] = __floats2half2_rn(fmaxf(av[6] + bB.z, 0.f), fmaxf(av[7] + bB.w, 0.f));
    *(float4*)(g_out1h + (size_t)node * F1 + col) = *(const float4*)pack;
}

// ---------------- conv2: fused softmax+aggregation (warp/node, smem-staged) --
__global__ __launch_bounds__(256) void agg2_k(const float* __restrict__ b2) {
    __shared__ int   sj[8][CAP];
    __shared__ float sw[8][CAP];
    int wslot = threadIdx.x >> 5, lane = threadIdx.x & 31;
    int node = blockIdx.x * 8 + wslot;
    if (node >= NN) return;
    int beg = g_off[node], deg = g_off[node + 1] - beg;   // CSR safe

    cudaGridDependencySynchronize();                       // wait for gemm2 outputs

    float ad = g_ad2[node];
    float den = 0.f;
    for (int kk = lane; kk < deg; kk += 32) {
        int j = g_srcidx[beg + kk];
        float e = __expf(lrelu(g_as2[j] + ad));
        den += e;
        if (kk < CAP) { sj[wslot][kk] = j; sw[wslot][kk] = e; }
    }
#pragma unroll
    for (int o = 16; o; o >>= 1) den += __shfl_xor_sync(0xffffffffu, den, o);
    float inv = 1.f / (den + 1e-16f);
    __syncwarp();

    float a0 = 0.f, a1 = 0.f;
    int c = lane * 2;
    int cap = deg < CAP ? deg : CAP;
    int kk = 0;
    for (; kk + 4 <= cap; kk += 4) {
        int j0 = sj[wslot][kk],     j1 = sj[wslot][kk + 1];
        int j2 = sj[wslot][kk + 2], j3 = sj[wslot][kk + 3];
        float w0 = sw[wslot][kk] * inv,     w1 = sw[wslot][kk + 1] * inv;
        float w2 = sw[wslot][kk + 2] * inv, w3 = sw[wslot][kk + 3] * inv;
        float2 v0 = __half22float2(*(const __half2*)(g_h2h + (size_t)j0 * OUTC + c));
        float2 v1 = __half22float2(*(const __half2*)(g_h2h + (size_t)j1 * OUTC + c));
        float2 v2 = __half22float2(*(const __half2*)(g_h2h + (size_t)j2 * OUTC + c));
        float2 v3 = __half22float2(*(const __half2*)(g_h2h + (size_t)j3 * OUTC + c));
        a0 += w0 * v0.x + w1 * v1.x + w2 * v2.x + w3 * v3.x;
        a1 += w0 * v0.y + w1 * v1.y + w2 * v2.y + w3 * v3.y;
    }
    for (; kk < cap; kk++) {
        int j0 = sj[wslot][kk];
        float w0 = sw[wslot][kk] * inv;
        float2 v0 = __half22float2(*(const __half2*)(g_h2h + (size_t)j0 * OUTC + c));
        a0 += w0 * v0.x; a1 += w0 * v0.y;
    }
    for (; kk < deg; kk++) {      // rare fallback
        int j0 = g_srcidx[beg + kk];
        float w0 = __expf(lrelu(g_as2[j0] + ad)) * inv;
        float2 v0 = __half22float2(*(const __half2*)(g_h2h + (size_t)j0 * OUTC + c));
        a0 += w0 * v0.x; a1 += w0 * v0.y;
    }
    float2 bb = *(const float2*)(b2 + c);
    *(__half2*)(g_out2h + (size_t)node * OUTC + c) = __floats2half2_rn(a0 + bb.x, a1 + bb.y);
}

// ---------------- decode: logits (8 lanes per edge, 4 edges per warp) --------
__global__ void decode_k(const int* __restrict__ pos, const int* __restrict__ neg,
                         float* __restrict__ out) {
    int g = blockIdx.x * blockDim.x + threadIdx.x;
    int e = g >> 3, lane = g & 7;
    if (e >= 2 * EE) return;
    int a, b;
    if (e < EE) { a = pos[e]; b = pos[EE + e]; }
    else        { int t = e - EE; a = neg[t]; b = neg[EE + t]; }

    cudaGridDependencySynchronize();      // index loads above overlap agg2 tail

    int c = lane * 8;
    float4 pa = *(const float4*)(g_out2h + (size_t)a * OUTC + c);
    float4 pb = *(const float4*)(g_out2h + (size_t)b * OUTC + c);
    const __half2* ha = (const __half2*)&pa;
    const __half2* hb = (const __half2*)&pb;
    float acc = 0.f;
#pragma unroll
    for (int i = 0; i < 4; i++) {
        float2 fa = __half22float2(ha[i]);
        float2 fb = __half22float2(hb[i]);
        acc += fa.x * fb.x + fa.y * fb.y;
    }
#pragma unroll
    for (int o = 4; o; o >>= 1) acc += __shfl_xor_sync(0xffffffffu, acc, o);
    if (!lane) out[e] = acc;
}

// ---------------- launch ----------------
extern "C" void kernel_launch(void* const* d_in, const int* in_sizes, int n_in,
                              void* d_out, int out_size) {
    const float* x    = (const float*)d_in[0];
    const int*   pos  = (const int*)d_in[1];
    const int*   neg  = (const int*)d_in[2];
    const float* W1   = (const float*)d_in[3];
    const float* as1v = (const float*)d_in[4];
    const float* ad1v = (const float*)d_in[5];
    const float* b1   = (const float*)d_in[6];
    const float* W2   = (const float*)d_in[7];
    const float* as2v = (const float*)d_in[8];
    const float* ad2v = (const float*)d_in[9];
    const float* b2   = (const float*)d_in[10];
    float* out = (float*)d_out;
    (void)in_sizes; (void)n_in; (void)out_size;

    static cudaStream_t s1 = nullptr;
    static cudaEvent_t evFork = nullptr, evJoin = nullptr;
    if (s1 == nullptr) {
        cudaStreamCreateWithFlags(&s1, cudaStreamNonBlocking);
        cudaEventCreateWithFlags(&evFork, cudaEventDisableTiming);
        cudaEventCreateWithFlags(&evJoin, cudaEventDisableTiming);
    }

    // PDL launch config (opportunistic overlap with preceding kernel)
    cudaLaunchAttribute pdlAttr[1];
    pdlAttr[0].id = cudaLaunchAttributeProgrammaticStreamSerialization;
    pdlAttr[0].val.programmaticStreamSerializationAllowed = 1;

    // fork: CSR build on s1, concurrent with gemm1 on the main stream
    cudaEventRecord(evFork, 0);
    cudaStreamWaitEvent(s1, evFork, 0);
    init_off_k<<<(NN + 256) / 256, 256, 0, s1>>>();
    hist_k<<<(EE + 255) / 256, 256, 0, s1>>>(pos);
    scan_k<<<1, 1024, 0, s1>>>();
    scatter_k<<<(ET + 255) / 256, 256, 0, s1>>>(pos);
    cudaEventRecord(evJoin, s1);

    // conv1 linear + fused attention dots (normal launch)
    mma_gemm_k<0><<<dim3(F1 / 64, (NN + 127) / 128), 256>>>(x, W1, as1v, ad1v, NN, F1, INC);

    cudaStreamWaitEvent(0, evJoin, 0);

    // agg1 (PDL secondary of gemm1)
    {
        cudaLaunchConfig_t cfg = {};
        cfg.gridDim = dim3((NN + 7) / 8); cfg.blockDim = dim3(256);
        cfg.stream = 0; cfg.attrs = pdlAttr; cfg.numAttrs = 1;
        cudaLaunchKernelEx(&cfg, agg1_k, b1);
    }
    // gemm2 (PDL secondary of agg1)
    {
        cudaLaunchConfig_t cfg = {};
        cfg.gridDim = dim3(OUTC / 64, (NN + 127) / 128); cfg.blockDim = dim3(256);
        cfg.stream = 0; cfg.attrs = pdlAttr; cfg.numAttrs = 1;
        cudaLaunchKernelEx(&cfg, mma_gemm_k<1>, (const float*)nullptr, W2, as2v, ad2v,
                           (int)NN, (int)OUTC, (int)F1);
    }
    // agg2 (PDL secondary of gemm2)
    {
        cudaLaunchConfig_t cfg = {};
        cfg.gridDim = dim3((NN + 7) / 8); cfg.blockDim = dim3(256);
        cfg.stream = 0; cfg.attrs = pdlAttr; cfg.numAttrs = 1;
        cudaLaunchKernelEx(&cfg, agg2_k, b2);
    }
    // decode (PDL secondary of agg2)
    {
        cudaLaunchConfig_t cfg = {};
        cfg.gridDim = dim3((2 * EE * 8 + 255) / 256); cfg.blockDim = dim3(256);
        cfg.stream = 0; cfg.attrs = pdlAttr; cfg.numAttrs = 1;
        cudaLaunchKernelEx(&cfg, decode_k, pos, neg, out);
    }
}

// round 16
// speedup vs baseline: 1.0621x; 1.0018x over previous
#include <cuda_runtime.h>
#include <cuda_fp16.h>
#include <math.h>
#include <stdint.h>

#define NN    50000
#define EE    800000
#define INC   128
#define HIDC  64
#define NH    4
#define OUTC  64
#define F1    (NH * HIDC)        // 256
#define ET    (EE + NN)          // edges + self loops = 850000

// ---------------- scratch (device globals; no allocation) ----------------
__device__ __half g_h1h  [(size_t)NN * F1];   // x @ W1   (fp16 storage)
__device__ __half g_out1h[(size_t)NN * F1];   // z        (fp16 storage)
__device__ float  g_as1 [NN * NH];
__device__ float  g_ad1 [NN * NH];
__device__ __half g_h2h [(size_t)NN * OUTC];  // z @ W2   (fp16 storage)
__device__ __half g_out2h[(size_t)NN * OUTC]; // z2       (fp16 storage)
__device__ float  g_as2 [NN];
__device__ float  g_ad2 [NN];
// CSR by destination (shared by both conv layers)
__device__ int    g_off [NN + 1];
__device__ int    g_fill[NN];
__device__ int    g_srcidx[ET];

__device__ __forceinline__ float lrelu(float v) { return v > 0.f ? v : 0.2f * v; }

// ---------------- CSR build ----------------
__global__ void init_off_k() {
    int i = blockIdx.x * blockDim.x + threadIdx.x;
    if (i <= NN) g_off[i] = (i == 0) ? 0 : 1;   // each node has 1 self loop
}

// 4 edges per thread: int4 load of dst indices, 4 independent atomics (MLP=4)
__global__ void hist_k(const int* __restrict__ ei) {
    int t = blockIdx.x * blockDim.x + threadIdx.x;
    int e = t * 4;
    if (e >= EE) return;
    int4 d4 = *(const int4*)(ei + EE + e);     // EE % 4 == 0, aligned
    atomicAdd(&g_off[d4.x + 1], 1);
    atomicAdd(&g_off[d4.y + 1], 1);
    atomicAdd(&g_off[d4.z + 1], 1);
    atomicAdd(&g_off[d4.w + 1], 1);
}

// single-block 3-phase inclusive scan over g_off[0..NN]
__global__ void scan_k() {
    const int L = NN + 1;
    const int CH = (L + 1023) / 1024;
    __shared__ int wsum[32];
    int t = threadIdx.x, lane = t & 31, wid = t >> 5;
    int beg = t * CH;
    int end = beg + CH; if (end > L) end = L;

    int s = 0;
    for (int i = beg; i < end; i++) s += g_off[i];

    int incl = s;
#pragma unroll
    for (int o = 1; o < 32; o <<= 1) {
        int v = __shfl_up_sync(0xffffffffu, incl, o);
        if (lane >= o) incl += v;
    }
    if (lane == 31) wsum[wid] = incl;
    __syncthreads();
    if (wid == 0) {
        int w = wsum[lane];
        int wi = w;
#pragma unroll
        for (int o = 1; o < 32; o <<= 1) {
            int v = __shfl_up_sync(0xffffffffu, wi, o);
            if (lane >= o) wi += v;
        }
        wsum[lane] = wi - w;
    }
    __syncthreads();

    int run = (incl - s) + wsum[wid];
    for (int i = beg; i < end; i++) {
        run += g_off[i];
        g_off[i] = run;
        if (i < NN) g_fill[i] = run;
    }
}

// 2 edges per thread: two independent atomic+store chains in flight (MLP=2)
__global__ void scatter_k(const int* __restrict__ ei) {
    int t = blockIdx.x * blockDim.x + threadIdx.x;
    int e0 = t * 2, e1 = t * 2 + 1;
    if (e0 >= ET) return;
    int s0, d0;
    if (e0 < EE) { s0 = ei[e0]; d0 = ei[EE + e0]; } else { s0 = d0 = e0 - EE; }
    int s1 = 0, d1 = 0;
    bool has1 = (e1 < ET);
    if (has1) {
        if (e1 < EE) { s1 = ei[e1]; d1 = ei[EE + e1]; } else { s1 = d1 = e1 - EE; }
    }
    int p0 = atomicAdd(&g_fill[d0], 1);
    int p1 = has1 ? atomicAdd(&g_fill[d1], 1) : 0;
    g_srcidx[p0] = s0;
    if (has1) g_srcidx[p1] = s1;
}

// ---------------- fp16 tensor-core GEMM + fused attention --------------------
// C[M,N] = A[M,K] @ B[K,N]; BM=128, BN=64, BK=16; 8 warps, each 32x32.
#define AS_STRIDE 18

__device__ __forceinline__ void mma_f16(float* d, uint32_t a0, uint32_t a1,
                                        uint32_t a2, uint32_t a3,
                                        uint32_t b0, uint32_t b1) {
    asm volatile(
        "mma.sync.aligned.m16n8k16.row.col.f32.f16.f16.f32 "
        "{%0,%1,%2,%3}, {%4,%5,%6,%7}, {%8,%9}, {%0,%1,%2,%3};\n"
        : "+f"(d[0]), "+f"(d[1]), "+f"(d[2]), "+f"(d[3])
        : "r"(a0), "r"(a1), "r"(a2), "r"(a3), "r"(b0), "r"(b1));
}

// MODE 0: A = x (fp32 ext), C = g_h1h,  attn -> g_as1/g_ad1 per head (blockIdx.x)
// MODE 1: A = g_out1h (fp16), C = g_h2h, attn -> g_as2/g_ad2   [PDL secondary]
template <int MODE>
__global__ __launch_bounds__(256) void mma_gemm_k(const float* __restrict__ Aext,
                                                  const float* __restrict__ B,
                                                  const float* __restrict__ att_s,
                                                  const float* __restrict__ att_d,
                                                  int M, int N, int K) {
    __shared__ __align__(16) __half As[128 * AS_STRIDE];
    __shared__ __align__(16) __half Bs[64 * AS_STRIDE];
    __shared__ float sAs[128], sAd[128];

    int tid = threadIdx.x;
    int wid = tid >> 5, lane = tid & 31;
    int warp_m = wid >> 1, warp_n = wid & 1;
    int m_warp = warp_m * 32, n_warp = warp_n * 32;
    int g = lane >> 2, c = lane & 3;
    int rowBase = blockIdx.y * 128, colBase = blockIdx.x * 64;

    if (MODE == 1) cudaGridDependencySynchronize();   // wait for agg1's z

    if (tid < 128) { sAs[tid] = 0.f; sAd[tid] = 0.f; }

    float acc[2][4][4] = {};

    for (int k0 = 0; k0 < K; k0 += 16) {
        // ---- stage A: 128 rows x 16 k (halves) ----
        {
            int row = tid >> 1, kq = (tid & 1) * 8;
            int gm = rowBase + row;
            __half2 hv[4];
            if (MODE == 0) {
                float4 v0 = make_float4(0.f, 0.f, 0.f, 0.f), v1 = v0;
                if (gm < M) {
                    const float* ap = Aext + (size_t)gm * K + k0 + kq;
                    v0 = *(const float4*)ap;
                    v1 = *(const float4*)(ap + 4);
                }
                hv[0] = __floats2half2_rn(v0.x, v0.y);
                hv[1] = __floats2half2_rn(v0.z, v0.w);
                hv[2] = __floats2half2_rn(v1.x, v1.y);
                hv[3] = __floats2half2_rn(v1.z, v1.w);
            } else {
                if (gm < M) {
                    float4 p = *(const float4*)(g_out1h + (size_t)gm * K + k0 + kq);
                    const __half2* hp = (const __half2*)&p;
                    hv[0] = hp[0]; hv[1] = hp[1]; hv[2] = hp[2]; hv[3] = hp[3];
                } else {
                    hv[0] = hv[1] = hv[2] = hv[3] = __floats2half2_rn(0.f, 0.f);
                }
            }
            __half2* dst = (__half2*)&As[row * AS_STRIDE + kq];
            dst[0] = hv[0]; dst[1] = hv[1]; dst[2] = hv[2]; dst[3] = hv[3];
        }
        // ---- stage B transposed: Bs[n][k], 16 k x 64 n ----
        {
            int kr = tid >> 4, nq = (tid & 15) * 4;
            float4 v = *(const float4*)(B + (size_t)(k0 + kr) * N + colBase + nq);
            Bs[(nq + 0) * AS_STRIDE + kr] = __float2half_rn(v.x);
            Bs[(nq + 1) * AS_STRIDE + kr] = __float2half_rn(v.y);
            Bs[(nq + 2) * AS_STRIDE + kr] = __float2half_rn(v.z);
            Bs[(nq + 3) * AS_STRIDE + kr] = __float2half_rn(v.w);
        }
        __syncthreads();

        uint32_t a[2][4], b[4][2];
#pragma unroll
        for (int t = 0; t < 2; t++) {
            int r0 = (m_warp + t * 16 + g) * AS_STRIDE + 2 * c;
            int r1 = r0 + 8 * AS_STRIDE;
            a[t][0] = *(const uint32_t*)&As[r0];
            a[t][1] = *(const uint32_t*)&As[r1];
            a[t][2] = *(const uint32_t*)&As[r0 + 8];
            a[t][3] = *(const uint32_t*)&As[r1 + 8];
        }
#pragma unroll
        for (int j = 0; j < 4; j++) {
            int nb = (n_warp + j * 8 + g) * AS_STRIDE + 2 * c;
            b[j][0] = *(const uint32_t*)&Bs[nb];
            b[j][1] = *(const uint32_t*)&Bs[nb + 8];
        }
#pragma unroll
        for (int t = 0; t < 2; t++)
#pragma unroll
            for (int j = 0; j < 4; j++)
                mma_f16(acc[t][j], a[t][0], a[t][1], a[t][2], a[t][3], b[j][0], b[j][1]);
        __syncthreads();
    }

    // write C as fp16
    __half* Ch = (MODE == 0) ? g_h1h : g_h2h;
#pragma unroll
    for (int t = 0; t < 2; t++)
#pragma unroll
        for (int j = 0; j < 4; j++) {
            int r0 = rowBase + m_warp + t * 16 + g;
            int r1 = r0 + 8;
            int cc = colBase + n_warp + j * 8 + 2 * c;
            if (r0 < M)
                *(__half2*)&Ch[(size_t)r0 * N + cc] = __floats2half2_rn(acc[t][j][0], acc[t][j][1]);
            if (r1 < M)
                *(__half2*)&Ch[(size_t)r1 * N + cc] = __floats2half2_rn(acc[t][j][2], acc[t][j][3]);
        }

    // fused attention dots over this block's 64 columns
#pragma unroll
    for (int t = 0; t < 2; t++) {
        float s0 = 0.f, d0 = 0.f, s1 = 0.f, d1 = 0.f;
#pragma unroll
        for (int j = 0; j < 4; j++) {
            int cg = colBase + n_warp + j * 8 + 2 * c;
            float w0 = __ldg(att_s + cg), w1 = __ldg(att_s + cg + 1);
            float v0 = __ldg(att_d + cg), v1 = __ldg(att_d + cg + 1);
            s0 += acc[t][j][0] * w0 + acc[t][j][1] * w1;
            d0 += acc[t][j][0] * v0 + acc[t][j][1] * v1;
            s1 += acc[t][j][2] * w0 + acc[t][j][3] * w1;
            d1 += acc[t][j][2] * v0 + acc[t][j][3] * v1;
        }
#pragma unroll
        for (int o = 1; o < 4; o <<= 1) {
            s0 += __shfl_xor_sync(0xffffffffu, s0, o);
            d0 += __shfl_xor_sync(0xffffffffu, d0, o);
            s1 += __shfl_xor_sync(0xffffffffu, s1, o);
            d1 += __shfl_xor_sync(0xffffffffu, d1, o);
        }
        if (c == 0) {
            int rl = m_warp + t * 16 + g;
            atomicAdd(&sAs[rl], s0);     atomicAdd(&sAd[rl], d0);
            atomicAdd(&sAs[rl + 8], s1); atomicAdd(&sAd[rl + 8], d1);
        }
    }
    __syncthreads();
    if (tid < 128) {
        int gm = rowBase + tid;
        if (gm < M) {
            if (MODE == 0) {
                g_as1[gm * NH + blockIdx.x] = sAs[tid];
                g_ad1[gm * NH + blockIdx.x] = sAd[tid];
            } else {
                g_as2[gm] = sAs[tid];
                g_ad2[gm] = sAd[tid];
            }
        }
    }
}

// ---------------- conv1: fused softmax+aggregation (warp/node, smem-staged) --
#define CAP 64
__global__ __launch_bounds__(256) void agg1_k(const float* __restrict__ b1) {
    __shared__ int    sj[8][CAP];
    __shared__ float4 se[8][CAP];
    int wslot = threadIdx.x >> 5, lane = threadIdx.x & 31;
    int node = blockIdx.x * 8 + wslot;
    if (node >= NN) return;
    int beg = g_off[node], deg = g_off[node + 1] - beg;   // CSR: event-ordered, safe

    cudaGridDependencySynchronize();                       // wait for gemm1 outputs

    float4 ad = *(const float4*)(g_ad1 + node * 4);
    float d0 = 0.f, d1 = 0.f, d2 = 0.f, d3 = 0.f;
    for (int kk = lane; kk < deg; kk += 32) {
        int j = g_srcidx[beg + kk];
        float4 as = *(const float4*)(g_as1 + j * 4);
        float e0 = __expf(lrelu(as.x + ad.x));
        float e1 = __expf(lrelu(as.y + ad.y));
        float e2 = __expf(lrelu(as.z + ad.z));
        float e3 = __expf(lrelu(as.w + ad.w));
        d0 += e0; d1 += e1; d2 += e2; d3 += e3;
        if (kk < CAP) { sj[wslot][kk] = j; se[wslot][kk] = make_float4(e0, e1, e2, e3); }
    }
#pragma unroll
    for (int o = 16; o; o >>= 1) {
        d0 += __shfl_xor_sync(0xffffffffu, d0, o);
        d1 += __shfl_xor_sync(0xffffffffu, d1, o);
        d2 += __shfl_xor_sync(0xffffffffu, d2, o);
        d3 += __shfl_xor_sync(0xffffffffu, d3, o);
    }
    float i0 = 1.f / (d0 + 1e-16f), i1 = 1.f / (d1 + 1e-16f);
    float i2 = 1.f / (d2 + 1e-16f), i3 = 1.f / (d3 + 1e-16f);
    __syncwarp();

    const bool s8 = (lane & 8) != 0, s16 = (lane & 16) != 0;
    float av[8] = {};
    int col = lane * 8;
    int cap = deg < CAP ? deg : CAP;

    int kk = 0;
    for (; kk + 4 <= cap; kk += 4) {
        int j0 = sj[wslot][kk],     j1 = sj[wslot][kk + 1];
        int j2 = sj[wslot][kk + 2], j3 = sj[wslot][kk + 3];
        float4 e0v = se[wslot][kk],     e1v = se[wslot][kk + 1];
        float4 e2v = se[wslot][kk + 2], e3v = se[wslot][kk + 3];
        float w0 = s16 ? (s8 ? e0v.w * i3 : e0v.z * i2) : (s8 ? e0v.y * i1 : e0v.x * i0);
        float w1 = s16 ? (s8 ? e1v.w * i3 : e1v.z * i2) : (s8 ? e1v.y * i1 : e1v.x * i0);
        float w2 = s16 ? (s8 ? e2v.w * i3 : e2v.z * i2) : (s8 ? e2v.y * i1 : e2v.x * i0);
        float w3 = s16 ? (s8 ? e3v.w * i3 : e3v.z * i2) : (s8 ? e3v.y * i1 : e3v.x * i0);
        float4 p0 = *(const float4*)(g_h1h + (size_t)j0 * F1 + col);
        float4 p1 = *(const float4*)(g_h1h + (size_t)j1 * F1 + col);
        float4 p2 = *(const float4*)(g_h1h + (size_t)j2 * F1 + col);
        float4 p3 = *(const float4*)(g_h1h + (size_t)j3 * F1 + col);
        const __half2* h0 = (const __half2*)&p0;
        const __half2* h1 = (const __half2*)&p1;
        const __half2* h2 = (const __half2*)&p2;
        const __half2* h3 = (const __half2*)&p3;
#pragma unroll
        for (int i = 0; i < 4; i++) {
            float2 f0 = __half22float2(h0[i]);
            float2 f1 = __half22float2(h1[i]);
            float2 f2 = __half22float2(h2[i]);
            float2 f3 = __half22float2(h3[i]);
            av[2 * i + 0] += w0 * f0.x + w1 * f1.x + w2 * f2.x + w3 * f3.x;
            av[2 * i + 1] += w0 * f0.y + w1 * f1.y + w2 * f2.y + w3 * f3.y;
        }
    }
    for (; kk < cap; kk++) {
        int j0 = sj[wslot][kk];
        float4 e0v = se[wslot][kk];
        float w0 = s16 ? (s8 ? e0v.w * i3 : e0v.z * i2) : (s8 ? e0v.y * i1 : e0v.x * i0);
        float4 p0 = *(const float4*)(g_h1h + (size_t)j0 * F1 + col);
        const __half2* h0 = (const __half2*)&p0;
#pragma unroll
        for (int i = 0; i < 4; i++) {
            float2 f0 = __half22float2(h0[i]);
            av[2 * i + 0] += w0 * f0.x;
            av[2 * i + 1] += w0 * f0.y;
        }
    }
    for (; kk < deg; kk++) {      // rare fallback: degree > CAP
        int j0 = g_srcidx[beg + kk];
        float4 as = *(const float4*)(g_as1 + j0 * 4);
        float e0 = __expf(lrelu(as.x + ad.x));
        float e1 = __expf(lrelu(as.y + ad.y));
        float e2 = __expf(lrelu(as.z + ad.z));
        float e3 = __expf(lrelu(as.w + ad.w));
        float w0 = s16 ? (s8 ? e3 * i3 : e2 * i2) : (s8 ? e1 * i1 : e0 * i0);
        float4 p0 = *(const float4*)(g_h1h + (size_t)j0 * F1 + col);
        const __half2* h0 = (const __half2*)&p0;
#pragma unroll
        for (int i = 0; i < 4; i++) {
            float2 f0 = __half22float2(h0[i]);
            av[2 * i + 0] += w0 * f0.x;
            av[2 * i + 1] += w0 * f0.y;
        }
    }

    float4 bA = *(const float4*)(b1 + col);
    float4 bB = *(const float4*)(b1 + col + 4);
    __half2 pack[4];
    pack[0] = __floats2half2_rn(fmaxf(av[0] + bA.x, 0.f), fmaxf(av[1] + bA.y, 0.f));
    pack[1] = __floats2half2_rn(fmaxf(av[2] + bA.z, 0.f), fmaxf(av[3] + bA.w, 0.f));
    pack[2] = __floats2half2_rn(fmaxf(av[4] + bB.x, 0.f), fmaxf(av[5] + bB.y, 0.f));
    pack[3] = __floats2half2_rn(fmaxf(av[6] + bB.z, 0.f), fmaxf(av[7] + bB.w, 0.f));
    *(float4*)(g_out1h + (size_t)node * F1 + col) = *(const float4*)pack;
}

// ---------------- conv2: fused softmax+aggregation (warp/node, smem-staged) --
__global__ __launch_bounds__(256) void agg2_k(const float* __restrict__ b2) {
    __shared__ int   sj[8][CAP];
    __shared__ float sw[8][CAP];
    int wslot = threadIdx.x >> 5, lane = threadIdx.x & 31;
    int node = blockIdx.x * 8 + wslot;
    if (node >= NN) return;
    int beg = g_off[node], deg = g_off[node + 1] - beg;   // CSR safe

    cudaGridDependencySynchronize();                       // wait for gemm2 outputs

    float ad = g_ad2[node];
    float den = 0.f;
    for (int kk = lane; kk < deg; kk += 32) {
        int j = g_srcidx[beg + kk];
        float e = __expf(lrelu(g_as2[j] + ad));
        den += e;
        if (kk < CAP) { sj[wslot][kk] = j; sw[wslot][kk] = e; }
    }
#pragma unroll
    for (int o = 16; o; o >>= 1) den += __shfl_xor_sync(0xffffffffu, den, o);
    float inv = 1.f / (den + 1e-16f);
    __syncwarp();

    float a0 = 0.f, a1 = 0.f;
    int c = lane * 2;
    int cap = deg < CAP ? deg : CAP;
    int kk = 0;
    for (; kk + 4 <= cap; kk += 4) {
        int j0 = sj[wslot][kk],     j1 = sj[wslot][kk + 1];
        int j2 = sj[wslot][kk + 2], j3 = sj[wslot][kk + 3];
        float w0 = sw[wslot][kk] * inv,     w1 = sw[wslot][kk + 1] * inv;
        float w2 = sw[wslot][kk + 2] * inv, w3 = sw[wslot][kk + 3] * inv;
        float2 v0 = __half22float2(*(const __half2*)(g_h2h + (size_t)j0 * OUTC + c));
        float2 v1 = __half22float2(*(const __half2*)(g_h2h + (size_t)j1 * OUTC + c));
        float2 v2 = __half22float2(*(const __half2*)(g_h2h + (size_t)j2 * OUTC + c));
        float2 v3 = __half22float2(*(const __half2*)(g_h2h + (size_t)j3 * OUTC + c));
        a0 += w0 * v0.x + w1 * v1.x + w2 * v2.x + w3 * v3.x;
        a1 += w0 * v0.y + w1 * v1.y + w2 * v2.y + w3 * v3.y;
    }
    for (; kk < cap; kk++) {
        int j0 = sj[wslot][kk];
        float w0 = sw[wslot][kk] * inv;
        float2 v0 = __half22float2(*(const __half2*)(g_h2h + (size_t)j0 * OUTC + c));
        a0 += w0 * v0.x; a1 += w0 * v0.y;
    }
    for (; kk < deg; kk++) {      // rare fallback
        int j0 = g_srcidx[beg + kk];
        float w0 = __expf(lrelu(g_as2[j0] + ad)) * inv;
        float2 v0 = __half22float2(*(const __half2*)(g_h2h + (size_t)j0 * OUTC + c));
        a0 += w0 * v0.x; a1 += w0 * v0.y;
    }
    float2 bb = *(const float2*)(b2 + c);
    *(__half2*)(g_out2h + (size_t)node * OUTC + c) = __floats2half2_rn(a0 + bb.x, a1 + bb.y);
}

// ---------------- decode: logits (8 lanes per edge, 4 edges per warp) --------
__global__ void decode_k(const int* __restrict__ pos, const int* __restrict__ neg,
                         float* __restrict__ out) {
    int g = blockIdx.x * blockDim.x + threadIdx.x;
    int e = g >> 3, lane = g & 7;
    if (e >= 2 * EE) return;
    int a, b;
    if (e < EE) { a = pos[e]; b = pos[EE + e]; }
    else        { int t = e - EE; a = neg[t]; b = neg[EE + t]; }

    cudaGridDependencySynchronize();      // index loads above overlap agg2 tail

    int c = lane * 8;
    float4 pa = *(const float4*)(g_out2h + (size_t)a * OUTC + c);
    float4 pb = *(const float4*)(g_out2h + (size_t)b * OUTC + c);
    const __half2* ha = (const __half2*)&pa;
    const __half2* hb = (const __half2*)&pb;
    float acc = 0.f;
#pragma unroll
    for (int i = 0; i < 4; i++) {
        float2 fa = __half22float2(ha[i]);
        float2 fb = __half22float2(hb[i]);
        acc += fa.x * fb.x + fa.y * fb.y;
    }
#pragma unroll
    for (int o = 4; o; o >>= 1) acc += __shfl_xor_sync(0xffffffffu, acc, o);
    if (!lane) out[e] = acc;
}

// ---------------- launch ----------------
extern "C" void kernel_launch(void* const* d_in, const int* in_sizes, int n_in,
                              void* d_out, int out_size) {
    const float* x    = (const float*)d_in[0];
    const int*   pos  = (const int*)d_in[1];
    const int*   neg  = (const int*)d_in[2];
    const float* W1   = (const float*)d_in[3];
    const float* as1v = (const float*)d_in[4];
    const float* ad1v = (const float*)d_in[5];
    const float* b1   = (const float*)d_in[6];
    const float* W2   = (const float*)d_in[7];
    const float* as2v = (const float*)d_in[8];
    const float* ad2v = (const float*)d_in[9];
    const float* b2   = (const float*)d_in[10];
    float* out = (float*)d_out;
    (void)in_sizes; (void)n_in; (void)out_size;

    static cudaStream_t s1 = nullptr;
    static cudaEvent_t evFork = nullptr, evJoin = nullptr;
    if (s1 == nullptr) {
        cudaStreamCreateWithFlags(&s1, cudaStreamNonBlocking);
        cudaEventCreateWithFlags(&evFork, cudaEventDisableTiming);
        cudaEventCreateWithFlags(&evJoin, cudaEventDisableTiming);
    }

    // PDL launch config (opportunistic overlap with preceding kernel)
    cudaLaunchAttribute pdlAttr[1];
    pdlAttr[0].id = cudaLaunchAttributeProgrammaticStreamSerialization;
    pdlAttr[0].val.programmaticStreamSerializationAllowed = 1;

    // fork: CSR build on s1, concurrent with gemm1 on the main stream
    cudaEventRecord(evFork, 0);
    cudaStreamWaitEvent(s1, evFork, 0);
    init_off_k<<<(NN + 256) / 256, 256, 0, s1>>>();
    hist_k<<<(EE / 4 + 255) / 256, 256, 0, s1>>>(pos);
    scan_k<<<1, 1024, 0, s1>>>();
    scatter_k<<<((ET + 1) / 2 + 255) / 256, 256, 0, s1>>>(pos);
    cudaEventRecord(evJoin, s1);

    // conv1 linear + fused attention dots (normal launch)
    mma_gemm_k<0><<<dim3(F1 / 64, (NN + 127) / 128), 256>>>(x, W1, as1v, ad1v, NN, F1, INC);

    cudaStreamWaitEvent(0, evJoin, 0);

    // agg1 (PDL secondary of gemm1)
    {
        cudaLaunchConfig_t cfg = {};
        cfg.gridDim = dim3((NN + 7) / 8); cfg.blockDim = dim3(256);
        cfg.stream = 0; cfg.attrs = pdlAttr; cfg.numAttrs = 1;
        cudaLaunchKernelEx(&cfg, agg1_k, b1);
    }
    // gemm2 (PDL secondary of agg1)
    {
        cudaLaunchConfig_t cfg = {};
        cfg.gridDim = dim3(OUTC / 64, (NN + 127) / 128); cfg.blockDim = dim3(256);
        cfg.stream = 0; cfg.attrs = pdlAttr; cfg.numAttrs = 1;
        cudaLaunchKernelEx(&cfg, mma_gemm_k<1>, (const float*)nullptr, W2, as2v, ad2v,
                           (int)NN, (int)OUTC, (int)F1);
    }
    // agg2 (PDL secondary of gemm2)
    {
        cudaLaunchConfig_t cfg = {};
        cfg.gridDim = dim3((NN + 7) / 8); cfg.blockDim = dim3(256);
        cfg.stream = 0; cfg.attrs = pdlAttr; cfg.numAttrs = 1;
        cudaLaunchKernelEx(&cfg, agg2_k, b2);
    }
    // decode (PDL secondary of agg2)
    {
        cudaLaunchConfig_t cfg = {};
        cfg.gridDim = dim3((2 * EE * 8 + 255) / 256); cfg.blockDim = dim3(256);
        cfg.stream = 0; cfg.attrs = pdlAttr; cfg.numAttrs = 1;
        cudaLaunchKernelEx(&cfg, decode_k, pos, neg, out);
    }
}

// round 17
// speedup vs baseline: 1.1114x; 1.0465x over previous
#include <cuda_runtime.h>
#include <cuda_fp16.h>
#include <math.h>
#include <stdint.h>

#define NN    50000
#define EE    800000
#define INC   128
#define HIDC  64
#define NH    4
#define OUTC  64
#define F1    (NH * HIDC)        // 256
#define ET    (EE + NN)          // edges + self loops = 850000

// ---------------- scratch (device globals; no allocation) ----------------
__device__ __half g_h1h  [(size_t)NN * F1];   // x @ W1   (fp16 storage)
__device__ __half g_out1h[(size_t)NN * F1];   // z        (fp16 storage)
__device__ float  g_as1 [NN * NH];
__device__ float  g_ad1 [NN * NH];
__device__ __half g_h2h [(size_t)NN * OUTC];  // z @ W2   (fp16 storage)
__device__ __half g_out2h[(size_t)NN * OUTC]; // z2       (fp16 storage)
__device__ float  g_as2 [NN];
__device__ float  g_ad2 [NN];
// CSR by destination (shared by both conv layers)
__device__ int    g_off [NN + 1];
__device__ int    g_fill[NN];
__device__ int    g_srcidx[ET];

__device__ __forceinline__ float lrelu(float v) { return v > 0.f ? v : 0.2f * v; }

// ---------------- CSR build ----------------
__global__ void init_off_k() {
    int i = blockIdx.x * blockDim.x + threadIdx.x;
    if (i <= NN) g_off[i] = (i == 0) ? 0 : 1;   // each node has 1 self loop
}

// 4 edges per thread: int4 load of dst indices, 4 independent atomics (MLP=4)
__global__ void hist_k(const int* __restrict__ ei) {
    int t = blockIdx.x * blockDim.x + threadIdx.x;
    int e = t * 4;
    if (e >= EE) return;
    int4 d4 = *(const int4*)(ei + EE + e);     // EE % 4 == 0, aligned
    atomicAdd(&g_off[d4.x + 1], 1);
    atomicAdd(&g_off[d4.y + 1], 1);
    atomicAdd(&g_off[d4.z + 1], 1);
    atomicAdd(&g_off[d4.w + 1], 1);
}

// single-block 3-phase inclusive scan over g_off[0..NN]
__global__ void scan_k() {
    const int L = NN + 1;
    const int CH = (L + 1023) / 1024;
    __shared__ int wsum[32];
    int t = threadIdx.x, lane = t & 31, wid = t >> 5;
    int beg = t * CH;
    int end = beg + CH; if (end > L) end = L;

    int s = 0;
    for (int i = beg; i < end; i++) s += g_off[i];

    int incl = s;
#pragma unroll
    for (int o = 1; o < 32; o <<= 1) {
        int v = __shfl_up_sync(0xffffffffu, incl, o);
        if (lane >= o) incl += v;
    }
    if (lane == 31) wsum[wid] = incl;
    __syncthreads();
    if (wid == 0) {
        int w = wsum[lane];
        int wi = w;
#pragma unroll
        for (int o = 1; o < 32; o <<= 1) {
            int v = __shfl_up_sync(0xffffffffu, wi, o);
            if (lane >= o) wi += v;
        }
        wsum[lane] = wi - w;
    }
    __syncthreads();

    int run = (incl - s) + wsum[wid];
    for (int i = beg; i < end; i++) {
        run += g_off[i];
        g_off[i] = run;
        if (i < NN) g_fill[i] = run;
    }
}

// 2 edges per thread: two independent atomic+store chains in flight (MLP=2)
__global__ void scatter_k(const int* __restrict__ ei) {
    int t = blockIdx.x * blockDim.x + threadIdx.x;
    int e0 = t * 2, e1 = t * 2 + 1;
    if (e0 >= ET) return;
    int s0, d0;
    if (e0 < EE) { s0 = ei[e0]; d0 = ei[EE + e0]; } else { s0 = d0 = e0 - EE; }
    int s1 = 0, d1 = 0;
    bool has1 = (e1 < ET);
    if (has1) {
        if (e1 < EE) { s1 = ei[e1]; d1 = ei[EE + e1]; } else { s1 = d1 = e1 - EE; }
    }
    int p0 = atomicAdd(&g_fill[d0], 1);
    int p1 = has1 ? atomicAdd(&g_fill[d1], 1) : 0;
    g_srcidx[p0] = s0;
    if (has1) g_srcidx[p1] = s1;
}

// ---------------- fp16 tensor-core GEMM + fused attention --------------------
// C[M,N] = A[M,K] @ B[K,N]; BM=128, BN=64, BK=16; 8 warps, each 32x32.
#define AS_STRIDE 18

__device__ __forceinline__ void mma_f16(float* d, uint32_t a0, uint32_t a1,
                                        uint32_t a2, uint32_t a3,
                                        uint32_t b0, uint32_t b1) {
    asm volatile(
        "mma.sync.aligned.m16n8k16.row.col.f32.f16.f16.f32 "
        "{%0,%1,%2,%3}, {%4,%5,%6,%7}, {%8,%9}, {%0,%1,%2,%3};\n"
        : "+f"(d[0]), "+f"(d[1]), "+f"(d[2]), "+f"(d[3])
        : "r"(a0), "r"(a1), "r"(a2), "r"(a3), "r"(b0), "r"(b1));
}

// MODE 0: A = x (fp32 ext), C = g_h1h,  attn -> g_as1/g_ad1 per head (blockIdx.x)
// MODE 1: A = g_out1h (fp16), C = g_h2h, attn -> g_as2/g_ad2   [PDL secondary]
template <int MODE>
__global__ __launch_bounds__(256) void mma_gemm_k(const float* __restrict__ Aext,
                                                  const float* __restrict__ B,
                                                  const float* __restrict__ att_s,
                                                  const float* __restrict__ att_d,
                                                  int M, int N, int K) {
    __shared__ __align__(16) __half As[128 * AS_STRIDE];
    __shared__ __align__(16) __half Bs[64 * AS_STRIDE];
    __shared__ float sAs[128], sAd[128];

    int tid = threadIdx.x;
    int wid = tid >> 5, lane = tid & 31;
    int warp_m = wid >> 1, warp_n = wid & 1;
    int m_warp = warp_m * 32, n_warp = warp_n * 32;
    int g = lane >> 2, c = lane & 3;
    int rowBase = blockIdx.y * 128, colBase = blockIdx.x * 64;

    if (MODE == 1) cudaGridDependencySynchronize();   // wait for agg1's z

    if (tid < 128) { sAs[tid] = 0.f; sAd[tid] = 0.f; }

    float acc[2][4][4] = {};

    for (int k0 = 0; k0 < K; k0 += 16) {
        // ---- stage A: 128 rows x 16 k (halves) ----
        {
            int row = tid >> 1, kq = (tid & 1) * 8;
            int gm = rowBase + row;
            __half2 hv[4];
            if (MODE == 0) {
                float4 v0 = make_float4(0.f, 0.f, 0.f, 0.f), v1 = v0;
                if (gm < M) {
                    const float* ap = Aext + (size_t)gm * K + k0 + kq;
                    v0 = *(const float4*)ap;
                    v1 = *(const float4*)(ap + 4);
                }
                hv[0] = __floats2half2_rn(v0.x, v0.y);
                hv[1] = __floats2half2_rn(v0.z, v0.w);
                hv[2] = __floats2half2_rn(v1.x, v1.y);
                hv[3] = __floats2half2_rn(v1.z, v1.w);
            } else {
                if (gm < M) {
                    float4 p = *(const float4*)(g_out1h + (size_t)gm * K + k0 + kq);
                    const __half2* hp = (const __half2*)&p;
                    hv[0] = hp[0]; hv[1] = hp[1]; hv[2] = hp[2]; hv[3] = hp[3];
                } else {
                    hv[0] = hv[1] = hv[2] = hv[3] = __floats2half2_rn(0.f, 0.f);
                }
            }
            __half2* dst = (__half2*)&As[row * AS_STRIDE + kq];
            dst[0] = hv[0]; dst[1] = hv[1]; dst[2] = hv[2]; dst[3] = hv[3];
        }
        // ---- stage B transposed: Bs[n][k], 16 k x 64 n ----
        {
            int kr = tid >> 4, nq = (tid & 15) * 4;
            float4 v = *(const float4*)(B + (size_t)(k0 + kr) * N + colBase + nq);
            Bs[(nq + 0) * AS_STRIDE + kr] = __float2half_rn(v.x);
            Bs[(nq + 1) * AS_STRIDE + kr] = __float2half_rn(v.y);
            Bs[(nq + 2) * AS_STRIDE + kr] = __float2half_rn(v.z);
            Bs[(nq + 3) * AS_STRIDE + kr] = __float2half_rn(v.w);
        }
        __syncthreads();

        uint32_t a[2][4], b[4][2];
#pragma unroll
        for (int t = 0; t < 2; t++) {
            int r0 = (m_warp + t * 16 + g) * AS_STRIDE + 2 * c;
            int r1 = r0 + 8 * AS_STRIDE;
            a[t][0] = *(const uint32_t*)&As[r0];
            a[t][1] = *(const uint32_t*)&As[r1];
            a[t][2] = *(const uint32_t*)&As[r0 + 8];
            a[t][3] = *(const uint32_t*)&As[r1 + 8];
        }
#pragma unroll
        for (int j = 0; j < 4; j++) {
            int nb = (n_warp + j * 8 + g) * AS_STRIDE + 2 * c;
            b[j][0] = *(const uint32_t*)&Bs[nb];
            b[j][1] = *(const uint32_t*)&Bs[nb + 8];
        }
#pragma unroll
        for (int t = 0; t < 2; t++)
#pragma unroll
            for (int j = 0; j < 4; j++)
                mma_f16(acc[t][j], a[t][0], a[t][1], a[t][2], a[t][3], b[j][0], b[j][1]);
        __syncthreads();
    }

    // write C as fp16
    __half* Ch = (MODE == 0) ? g_h1h : g_h2h;
#pragma unroll
    for (int t = 0; t < 2; t++)
#pragma unroll
        for (int j = 0; j < 4; j++) {
            int r0 = rowBase + m_warp + t * 16 + g;
            int r1 = r0 + 8;
            int cc = colBase + n_warp + j * 8 + 2 * c;
            if (r0 < M)
                *(__half2*)&Ch[(size_t)r0 * N + cc] = __floats2half2_rn(acc[t][j][0], acc[t][j][1]);
            if (r1 < M)
                *(__half2*)&Ch[(size_t)r1 * N + cc] = __floats2half2_rn(acc[t][j][2], acc[t][j][3]);
        }

    // fused attention dots over this block's 64 columns
#pragma unroll
    for (int t = 0; t < 2; t++) {
        float s0 = 0.f, d0 = 0.f, s1 = 0.f, d1 = 0.f;
#pragma unroll
        for (int j = 0; j < 4; j++) {
            int cg = colBase + n_warp + j * 8 + 2 * c;
            float w0 = __ldg(att_s + cg), w1 = __ldg(att_s + cg + 1);
            float v0 = __ldg(att_d + cg), v1 = __ldg(att_d + cg + 1);
            s0 += acc[t][j][0] * w0 + acc[t][j][1] * w1;
            d0 += acc[t][j][0] * v0 + acc[t][j][1] * v1;
            s1 += acc[t][j][2] * w0 + acc[t][j][3] * w1;
            d1 += acc[t][j][2] * v0 + acc[t][j][3] * v1;
        }
#pragma unroll
        for (int o = 1; o < 4; o <<= 1) {
            s0 += __shfl_xor_sync(0xffffffffu, s0, o);
            d0 += __shfl_xor_sync(0xffffffffu, d0, o);
            s1 += __shfl_xor_sync(0xffffffffu, s1, o);
            d1 += __shfl_xor_sync(0xffffffffu, d1, o);
        }
        if (c == 0) {
            int rl = m_warp + t * 16 + g;
            atomicAdd(&sAs[rl], s0);     atomicAdd(&sAd[rl], d0);
            atomicAdd(&sAs[rl + 8], s1); atomicAdd(&sAd[rl + 8], d1);
        }
    }
    __syncthreads();
    if (tid < 128) {
        int gm = rowBase + tid;
        if (gm < M) {
            if (MODE == 0) {
                g_as1[gm * NH + blockIdx.x] = sAs[tid];
                g_ad1[gm * NH + blockIdx.x] = sAd[tid];
            } else {
                g_as2[gm] = sAs[tid];
                g_ad2[gm] = sAd[tid];
            }
        }
    }
}

// ---------------- conv1: fused softmax+aggregation (warp/node, smem-staged) --
// srcidx staged into smem BEFORE the PDL sync (CSR is event-ordered, not
// producer-dependent) — overlaps the random index gather with gemm1's drain.
#define CAP 64
__global__ __launch_bounds__(256) void agg1_k(const float* __restrict__ b1) {
    __shared__ int    sj[8][CAP];
    __shared__ float4 se[8][CAP];
    int wslot = threadIdx.x >> 5, lane = threadIdx.x & 31;
    int node = blockIdx.x * 8 + wslot;
    if (node >= NN) return;
    int beg = g_off[node], deg = g_off[node + 1] - beg;

    // pre-sync: stage neighbor indices (depends only on CSR chain)
    int cap = deg < CAP ? deg : CAP;
    for (int kk = lane; kk < cap; kk += 32) sj[wslot][kk] = g_srcidx[beg + kk];
    __syncwarp();

    cudaGridDependencySynchronize();                       // wait for gemm1 outputs

    float4 ad = *(const float4*)(g_ad1 + node * 4);
    float d0 = 0.f, d1 = 0.f, d2 = 0.f, d3 = 0.f;
    for (int kk = lane; kk < deg; kk += 32) {
        int j = (kk < CAP) ? sj[wslot][kk] : g_srcidx[beg + kk];
        float4 as = *(const float4*)(g_as1 + j * 4);
        float e0 = __expf(lrelu(as.x + ad.x));
        float e1 = __expf(lrelu(as.y + ad.y));
        float e2 = __expf(lrelu(as.z + ad.z));
        float e3 = __expf(lrelu(as.w + ad.w));
        d0 += e0; d1 += e1; d2 += e2; d3 += e3;
        if (kk < CAP) se[wslot][kk] = make_float4(e0, e1, e2, e3);
    }
#pragma unroll
    for (int o = 16; o; o >>= 1) {
        d0 += __shfl_xor_sync(0xffffffffu, d0, o);
        d1 += __shfl_xor_sync(0xffffffffu, d1, o);
        d2 += __shfl_xor_sync(0xffffffffu, d2, o);
        d3 += __shfl_xor_sync(0xffffffffu, d3, o);
    }
    float i0 = 1.f / (d0 + 1e-16f), i1 = 1.f / (d1 + 1e-16f);
    float i2 = 1.f / (d2 + 1e-16f), i3 = 1.f / (d3 + 1e-16f);
    __syncwarp();

    const bool s8 = (lane & 8) != 0, s16 = (lane & 16) != 0;
    float av[8] = {};
    int col = lane * 8;

    int kk = 0;
    for (; kk + 4 <= cap; kk += 4) {
        int j0 = sj[wslot][kk],     j1 = sj[wslot][kk + 1];
        int j2 = sj[wslot][kk + 2], j3 = sj[wslot][kk + 3];
        float4 e0v = se[wslot][kk],     e1v = se[wslot][kk + 1];
        float4 e2v = se[wslot][kk + 2], e3v = se[wslot][kk + 3];
        float w0 = s16 ? (s8 ? e0v.w * i3 : e0v.z * i2) : (s8 ? e0v.y * i1 : e0v.x * i0);
        float w1 = s16 ? (s8 ? e1v.w * i3 : e1v.z * i2) : (s8 ? e1v.y * i1 : e1v.x * i0);
        float w2 = s16 ? (s8 ? e2v.w * i3 : e2v.z * i2) : (s8 ? e2v.y * i1 : e2v.x * i0);
        float w3 = s16 ? (s8 ? e3v.w * i3 : e3v.z * i2) : (s8 ? e3v.y * i1 : e3v.x * i0);
        float4 p0 = *(const float4*)(g_h1h + (size_t)j0 * F1 + col);
        float4 p1 = *(const float4*)(g_h1h + (size_t)j1 * F1 + col);
        float4 p2 = *(const float4*)(g_h1h + (size_t)j2 * F1 + col);
        float4 p3 = *(const float4*)(g_h1h + (size_t)j3 * F1 + col);
        const __half2* h0 = (const __half2*)&p0;
        const __half2* h1 = (const __half2*)&p1;
        const __half2* h2 = (const __half2*)&p2;
        const __half2* h3 = (const __half2*)&p3;
#pragma unroll
        for (int i = 0; i < 4; i++) {
            float2 f0 = __half22float2(h0[i]);
            float2 f1 = __half22float2(h1[i]);
            float2 f2 = __half22float2(h2[i]);
            float2 f3 = __half22float2(h3[i]);
            av[2 * i + 0] += w0 * f0.x + w1 * f1.x + w2 * f2.x + w3 * f3.x;
            av[2 * i + 1] += w0 * f0.y + w1 * f1.y + w2 * f2.y + w3 * f3.y;
        }
    }
    for (; kk < cap; kk++) {
        int j0 = sj[wslot][kk];
        float4 e0v = se[wslot][kk];
        float w0 = s16 ? (s8 ? e0v.w * i3 : e0v.z * i2) : (s8 ? e0v.y * i1 : e0v.x * i0);
        float4 p0 = *(const float4*)(g_h1h + (size_t)j0 * F1 + col);
        const __half2* h0 = (const __half2*)&p0;
#pragma unroll
        for (int i = 0; i < 4; i++) {
            float2 f0 = __half22float2(h0[i]);
            av[2 * i + 0] += w0 * f0.x;
            av[2 * i + 1] += w0 * f0.y;
        }
    }
    for (; kk < deg; kk++) {      // rare fallback: degree > CAP
        int j0 = g_srcidx[beg + kk];
        float4 as = *(const float4*)(g_as1 + j0 * 4);
        float e0 = __expf(lrelu(as.x + ad.x));
        float e1 = __expf(lrelu(as.y + ad.y));
        float e2 = __expf(lrelu(as.z + ad.z));
        float e3 = __expf(lrelu(as.w + ad.w));
        float w0 = s16 ? (s8 ? e3 * i3 : e2 * i2) : (s8 ? e1 * i1 : e0 * i0);
        float4 p0 = *(const float4*)(g_h1h + (size_t)j0 * F1 + col);
        const __half2* h0 = (const __half2*)&p0;
#pragma unroll
        for (int i = 0; i < 4; i++) {
            float2 f0 = __half22float2(h0[i]);
            av[2 * i + 0] += w0 * f0.x;
            av[2 * i + 1] += w0 * f0.y;
        }
    }

    float4 bA = *(const float4*)(b1 + col);
    float4 bB = *(const float4*)(b1 + col + 4);
    __half2 pack[4];
    pack[0] = __floats2half2_rn(fmaxf(av[0] + bA.x, 0.f), fmaxf(av[1] + bA.y, 0.f));
    pack[1] = __floats2half2_rn(fmaxf(av[2] + bA.z, 0.f), fmaxf(av[3] + bA.w, 0.f));
    pack[2] = __floats2half2_rn(fmaxf(av[4] + bB.x, 0.f), fmaxf(av[5] + bB.y, 0.f));
    pack[3] = __floats2half2_rn(fmaxf(av[6] + bB.z, 0.f), fmaxf(av[7] + bB.w, 0.f));
    *(float4*)(g_out1h + (size_t)node * F1 + col) = *(const float4*)pack;
}

// ---------------- conv2: fused softmax+aggregation (warp/node, smem-staged) --
__global__ __launch_bounds__(256) void agg2_k(const float* __restrict__ b2) {
    __shared__ int   sj[8][CAP];
    __shared__ float sw[8][CAP];
    int wslot = threadIdx.x >> 5, lane = threadIdx.x & 31;
    int node = blockIdx.x * 8 + wslot;
    if (node >= NN) return;
    int beg = g_off[node], deg = g_off[node + 1] - beg;

    // pre-sync: stage neighbor indices (CSR only)
    int cap = deg < CAP ? deg : CAP;
    for (int kk = lane; kk < cap; kk += 32) sj[wslot][kk] = g_srcidx[beg + kk];
    __syncwarp();

    cudaGridDependencySynchronize();                       // wait for gemm2 outputs

    float ad = g_ad2[node];
    float den = 0.f;
    for (int kk = lane; kk < deg; kk += 32) {
        int j = (kk < CAP) ? sj[wslot][kk] : g_srcidx[beg + kk];
        float e = __expf(lrelu(g_as2[j] + ad));
        den += e;
        if (kk < CAP) sw[wslot][kk] = e;
    }
#pragma unroll
    for (int o = 16; o; o >>= 1) den += __shfl_xor_sync(0xffffffffu, den, o);
    float inv = 1.f / (den + 1e-16f);
    __syncwarp();

    float a0 = 0.f, a1 = 0.f;
    int c = lane * 2;
    int kk = 0;
    for (; kk + 4 <= cap; kk += 4) {
        int j0 = sj[wslot][kk],     j1 = sj[wslot][kk + 1];
        int j2 = sj[wslot][kk + 2], j3 = sj[wslot][kk + 3];
        float w0 = sw[wslot][kk] * inv,     w1 = sw[wslot][kk + 1] * inv;
        float w2 = sw[wslot][kk + 2] * inv, w3 = sw[wslot][kk + 3] * inv;
        float2 v0 = __half22float2(*(const __half2*)(g_h2h + (size_t)j0 * OUTC + c));
        float2 v1 = __half22float2(*(const __half2*)(g_h2h + (size_t)j1 * OUTC + c));
        float2 v2 = __half22float2(*(const __half2*)(g_h2h + (size_t)j2 * OUTC + c));
        float2 v3 = __half22float2(*(const __half2*)(g_h2h + (size_t)j3 * OUTC + c));
        a0 += w0 * v0.x + w1 * v1.x + w2 * v2.x + w3 * v3.x;
        a1 += w0 * v0.y + w1 * v1.y + w2 * v2.y + w3 * v3.y;
    }
    for (; kk < cap; kk++) {
        int j0 = sj[wslot][kk];
        float w0 = sw[wslot][kk] * inv;
        float2 v0 = __half22float2(*(const __half2*)(g_h2h + (size_t)j0 * OUTC + c));
        a0 += w0 * v0.x; a1 += w0 * v0.y;
    }
    for (; kk < deg; kk++) {      // rare fallback
        int j0 = g_srcidx[beg + kk];
        float w0 = __expf(lrelu(g_as2[j0] + ad)) * inv;
        float2 v0 = __half22float2(*(const __half2*)(g_h2h + (size_t)j0 * OUTC + c));
        a0 += w0 * v0.x; a1 += w0 * v0.y;
    }
    float2 bb = *(const float2*)(b2 + c);
    *(__half2*)(g_out2h + (size_t)node * OUTC + c) = __floats2half2_rn(a0 + bb.x, a1 + bb.y);
}

// ---------------- decode: logits (4 lanes per edge, 8 edges per warp) --------
__global__ void decode_k(const int* __restrict__ pos, const int* __restrict__ neg,
                         float* __restrict__ out) {
    int g = blockIdx.x * blockDim.x + threadIdx.x;
    int e = g >> 2, lane = g & 3;
    if (e >= 2 * EE) return;
    int a, b;
    if (e < EE) { a = pos[e]; b = pos[EE + e]; }
    else        { int t = e - EE; a = neg[t]; b = neg[EE + t]; }

    cudaGridDependencySynchronize();      // index loads above overlap agg2 tail

    int c = lane * 16;
    const float4* pa = (const float4*)(g_out2h + (size_t)a * OUTC + c);
    const float4* pb = (const float4*)(g_out2h + (size_t)b * OUTC + c);
    float4 qa0 = pa[0], qa1 = pa[1];
    float4 qb0 = pb[0], qb1 = pb[1];
    const __half2* ha0 = (const __half2*)&qa0;
    const __half2* ha1 = (const __half2*)&qa1;
    const __half2* hb0 = (const __half2*)&qb0;
    const __half2* hb1 = (const __half2*)&qb1;
    float acc = 0.f;
#pragma unroll
    for (int i = 0; i < 4; i++) {
        float2 fa = __half22float2(ha0[i]);
        float2 fb = __half22float2(hb0[i]);
        acc += fa.x * fb.x + fa.y * fb.y;
        float2 ga = __half22float2(ha1[i]);
        float2 gb = __half22float2(hb1[i]);
        acc += ga.x * gb.x + ga.y * gb.y;
    }
#pragma unroll
    for (int o = 2; o; o >>= 1) acc += __shfl_xor_sync(0xffffffffu, acc, o);
    if (!lane) out[e] = acc;
}

// ---------------- launch ----------------
extern "C" void kernel_launch(void* const* d_in, const int* in_sizes, int n_in,
                              void* d_out, int out_size) {
    const float* x    = (const float*)d_in[0];
    const int*   pos  = (const int*)d_in[1];
    const int*   neg  = (const int*)d_in[2];
    const float* W1   = (const float*)d_in[3];
    const float* as1v = (const float*)d_in[4];
    const float* ad1v = (const float*)d_in[5];
    const float* b1   = (const float*)d_in[6];
    const float* W2   = (const float*)d_in[7];
    const float* as2v = (const float*)d_in[8];
    const float* ad2v = (const float*)d_in[9];
    const float* b2   = (const float*)d_in[10];
    float* out = (float*)d_out;
    (void)in_sizes; (void)n_in; (void)out_size;

    static cudaStream_t s1 = nullptr;
    static cudaEvent_t evFork = nullptr, evJoin = nullptr;
    if (s1 == nullptr) {
        cudaStreamCreateWithFlags(&s1, cudaStreamNonBlocking);
        cudaEventCreateWithFlags(&evFork, cudaEventDisableTiming);
        cudaEventCreateWithFlags(&evJoin, cudaEventDisableTiming);
    }

    // PDL launch config (opportunistic overlap with preceding kernel)
    cudaLaunchAttribute pdlAttr[1];
    pdlAttr[0].id = cudaLaunchAttributeProgrammaticStreamSerialization;
    pdlAttr[0].val.programmaticStreamSerializationAllowed = 1;

    // fork: CSR build on s1, concurrent with gemm1 on the main stream
    cudaEventRecord(evFork, 0);
    cudaStreamWaitEvent(s1, evFork, 0);
    init_off_k<<<(NN + 256) / 256, 256, 0, s1>>>();
    hist_k<<<(EE / 4 + 255) / 256, 256, 0, s1>>>(pos);
    scan_k<<<1, 1024, 0, s1>>>();
    scatter_k<<<((ET + 1) / 2 + 255) / 256, 256, 0, s1>>>(pos);
    cudaEventRecord(evJoin, s1);

    // conv1 linear + fused attention dots (normal launch)
    mma_gemm_k<0><<<dim3(F1 / 64, (NN + 127) / 128), 256>>>(x, W1, as1v, ad1v, NN, F1, INC);

    cudaStreamWaitEvent(0, evJoin, 0);

    // agg1 (PDL secondary of gemm1)
    {
        cudaLaunchConfig_t cfg = {};
        cfg.gridDim = dim3((NN + 7) / 8); cfg.blockDim = dim3(256);
        cfg.stream = 0; cfg.attrs = pdlAttr; cfg.numAttrs = 1;
        cudaLaunchKernelEx(&cfg, agg1_k, b1);
    }
    // gemm2 (PDL secondary of agg1)
    {
        cudaLaunchConfig_t cfg = {};
        cfg.gridDim = dim3(OUTC / 64, (NN + 127) / 128); cfg.blockDim = dim3(256);
        cfg.stream = 0; cfg.attrs = pdlAttr; cfg.numAttrs = 1;
        cudaLaunchKernelEx(&cfg, mma_gemm_k<1>, (const float*)nullptr, W2, as2v, ad2v,
                           (int)NN, (int)OUTC, (int)F1);
    }
    // agg2 (PDL secondary of gemm2)
    {
        cudaLaunchConfig_t cfg = {};
        cfg.gridDim = dim3((NN + 7) / 8); cfg.blockDim = dim3(256);
        cfg.stream = 0; cfg.attrs = pdlAttr; cfg.numAttrs = 1;
        cudaLaunchKernelEx(&cfg, agg2_k, b2);
    }
    // decode (PDL secondary of agg2)
    {
        cudaLaunchConfig_t cfg = {};
        cfg.gridDim = dim3((2 * EE * 4 + 255) / 256); cfg.blockDim = dim3(256);
        cfg.stream = 0; cfg.attrs = pdlAttr; cfg.numAttrs = 1;
        cudaLaunchKernelEx(&cfg, decode_k, pos, neg, out);
    }
}